// round 10
// baseline (speedup 1.0000x reference)
#include <cuda_runtime.h>
#include <cuda_bf16.h>
#include <cstdint>

#define B_   32
#define N_   2048
#define F_   1024
#define OUT_ 1024
#define HS_  8192
#define HF_  4096

// ---------------------------------------------------------------------------
// Scratch (__device__ globals; allocation-free rule).
// ---------------------------------------------------------------------------
__device__ __align__(1024) unsigned char g_xm [268435456];   // xm fp32 -> y fp32 -> z int8-packed
__device__ __align__(1024) unsigned char g_xs [268435456];   // xs fp32 (skip) -> z fp32
__device__ __align__(1024) unsigned char g_xsp[268435456];   // xs int8-packed -> zt fp32
__device__ __align__(1024) unsigned char g_p  [268435456];   // argsort indices (int)
__device__ __align__(1024) unsigned char g_h  [1073741824];  // h int8-packed -> h2 int8-packed
__device__ __align__(1024) unsigned char g_w1 [33554432];    // 8192 x 2048 x 2B
__device__ __align__(1024) unsigned char g_w2 [33554432];    // 2048 x 8192 x 2B
__device__ __align__(1024) unsigned char g_w3 [8388608];     // 4096 x 1024 x 2B
__device__ __align__(1024) unsigned char g_w4 [8388608];     // 1024 x 4096 x 2B
__device__ float g_sc[262144];   // per-row scales: [0)xs32768 [32768)w1 [40960)w2 [43008)w3 [47104)w4 [65536)z65536

#define SC_XS 0
#define SC_W1 32768
#define SC_W2 40960
#define SC_W3 43008
#define SC_W4 47104
#define SC_Z  65536

// ---------------------------------------------------------------------------
// PTX helpers (plain sm_75/sm_90 ISA — no 'a'-suffix features)
// ---------------------------------------------------------------------------
__device__ __forceinline__ uint32_t smem_u32(const void* p) {
    uint32_t a;
    asm("{ .reg .u64 t; cvta.to.shared.u64 t, %1; cvt.u32.u64 %0, t; }" : "=r"(a) : "l"(p));
    return a;
}
__device__ __forceinline__ void mbar_init(uint32_t m, uint32_t cnt) {
    asm volatile("mbarrier.init.shared.b64 [%0], %1;" :: "r"(m), "r"(cnt) : "memory");
}
__device__ __forceinline__ void mbar_wait(uint32_t m, uint32_t parity) {
    uint32_t done = 0;
    while (!done) {
        asm volatile(
            "{\n\t.reg .pred p;\n\t"
            "mbarrier.try_wait.parity.acquire.cta.shared::cta.b64 p, [%1], %2, 0x989680;\n\t"
            "selp.b32 %0, 1, 0, p;\n\t}"
            : "=r"(done) : "r"(m), "r"(parity) : "memory");
    }
}
__device__ __forceinline__ void mbar_arrive(uint32_t m) {
    asm volatile("mbarrier.arrive.shared.b64 _, [%0];" :: "r"(m) : "memory");
}
__device__ __forceinline__ void mbar_expect_tx(uint32_t m, uint32_t bytes) {
    asm volatile("mbarrier.arrive.expect_tx.shared.b64 _, [%0], %1;" :: "r"(m), "r"(bytes) : "memory");
}
__device__ __forceinline__ void bulk_cp(uint32_t dst, const void* src, uint32_t bytes, uint32_t mbar) {
    asm volatile("cp.async.bulk.shared::cta.global.mbarrier::complete_tx::bytes [%0], [%1], %2, [%3];"
                 :: "r"(dst), "l"(src), "r"(bytes), "r"(mbar) : "memory");
}
__device__ __forceinline__ void ldm_x4(uint32_t* r, uint32_t addr) {
    asm volatile("ldmatrix.sync.aligned.m8n8.x4.shared.b16 {%0,%1,%2,%3}, [%4];"
                 : "=r"(r[0]), "=r"(r[1]), "=r"(r[2]), "=r"(r[3]) : "r"(addr));
}
__device__ __forceinline__ void mma_s8(int* d, const uint32_t* a, uint32_t b0, uint32_t b1) {
    asm volatile("mma.sync.aligned.m16n8k32.row.col.s32.s8.s8.s32 "
                 "{%0,%1,%2,%3}, {%4,%5,%6,%7}, {%8,%9}, {%0,%1,%2,%3};"
                 : "+r"(d[0]), "+r"(d[1]), "+r"(d[2]), "+r"(d[3])
                 : "r"(a[0]), "r"(a[1]), "r"(a[2]), "r"(a[3]), "r"(b0), "r"(b1));
}

// dual int8 quantization: v ~= s*(q1 + q2/256), |err| <= s/512
__device__ __forceinline__ void quant1(float v, float s, float inv, int& q1, int& q2) {
    q1 = __float2int_rn(v * inv);
    q1 = max(-127, min(127, q1));
    float r = v - (float)q1 * s;
    q2 = __float2int_rn(r * inv * 256.f);
    q2 = max(-128, min(127, q2));
}

// ---------------------------------------------------------------------------
// Packed-tiled int8 layout: rows in 128-groups, K in 64-groups.
// Tile (t, kc) = 16KB: 128 rows x 128B, row = [q1 x64 | q2 x64],
// byte offset pre-swizzled with o ^ ((row&7)<<4).
// ---------------------------------------------------------------------------
__device__ __forceinline__ void pack_store4(unsigned char* base, int NC, int r, int k0,
                                            const float* v, float s, float inv) {
    uint32_t q1w = 0, q2w = 0;
#pragma unroll
    for (int j = 0; j < 4; j++) {
        int q1, q2;
        quant1(v[j], s, inv, q1, q2);
        q1w |= ((uint32_t)(q1 & 0xff)) << (8 * j);
        q2w |= ((uint32_t)(q2 & 0xff)) << (8 * j);
    }
    size_t tb = (((size_t)(r >> 7) * NC + (k0 >> 6)) * 128 + (r & 127)) * 128;
    int j = k0 & 63, swz = (r & 7) << 4;
    *(uint32_t*)(base + tb + (j ^ swz)) = q1w;
    *(uint32_t*)(base + tb + ((j + 64) ^ swz)) = q2w;
}

// ---------------------------------------------------------------------------
// transpose / sort / gather / row-pack
// ---------------------------------------------------------------------------
__global__ void transpose_k(const float* __restrict__ src, float* __restrict__ dst,
                            int R, int C) {
    __shared__ float tile[32][33];
    size_t bo = (size_t)blockIdx.z * R * C;
    int r0 = blockIdx.y * 32, c0 = blockIdx.x * 32;
    int tx = threadIdx.x, ty = threadIdx.y;
#pragma unroll
    for (int i = 0; i < 32; i += 8)
        tile[ty + i][tx] = src[bo + (size_t)(r0 + ty + i) * C + (c0 + tx)];
    __syncthreads();
#pragma unroll
    for (int i = 0; i < 32; i += 8)
        dst[bo + (size_t)(c0 + ty + i) * R + (r0 + tx)] = tile[tx][ty + i];
}

__global__ __launch_bounds__(512) void sort_k(const float* __restrict__ xm,
                                              float* __restrict__ xs,
                                              unsigned char* __restrict__ xsp,
                                              float* __restrict__ sc,
                                              int* __restrict__ p) {
    __shared__ unsigned long long key[2048];
    __shared__ float val[2048];
    __shared__ int   rnk[2048];
    __shared__ float red[512];
    size_t base = (size_t)blockIdx.x * 2048;
    int tid = threadIdx.x;

    float mx = 0.f;
    for (int i = tid; i < 2048; i += 512) {
        float v = xm[base + i];
        val[i] = v;
        mx = fmaxf(mx, fabsf(v));
        unsigned u = __float_as_uint(v);
        u = (u & 0x80000000u) ? ~u : (u | 0x80000000u);
        key[i] = ((unsigned long long)u << 32) | (unsigned)i;
    }
    red[tid] = mx;
    __syncthreads();

    for (int k2 = 2; k2 <= 2048; k2 <<= 1) {
        for (int j = k2 >> 1; j > 0; j >>= 1) {
            for (int i = tid; i < 2048; i += 512) {
                int l = i ^ j;
                if (l > i) {
                    unsigned long long a = key[i], b = key[l];
                    bool asc = ((i & k2) == 0);
                    if ((a > b) == asc) { key[i] = b; key[l] = a; }
                }
            }
            __syncthreads();
        }
    }

    for (int st = 256; st > 0; st >>= 1) {
        if (tid < st) red[tid] = fmaxf(red[tid], red[tid + st]);
        __syncthreads();
    }
    float rmax = fmaxf(red[0], 1e-20f);
    float s = rmax / 127.f, inv = 127.f / rmax;
    if (tid == 0) sc[blockIdx.x] = s;

    for (int i = tid; i < 2048; i += 512) {
        int pi = (int)(unsigned)(key[i] & 0xffffffffu);
        p[base + i] = pi;
        rnk[pi] = i;
    }
    __syncthreads();
    int r = blockIdx.x;
    {
        int i0 = tid * 4;
        float v[4];
#pragma unroll
        for (int j = 0; j < 4; j++) {
            v[j] = val[rnk[i0 + j]];
            xs[base + i0 + j] = v[j];
        }
        pack_store4(xsp, 32, r, i0, v, s, inv);   // NC = 2048/64
    }
}

__global__ __launch_bounds__(512) void gather_k(const float* __restrict__ y,
                                                const int* __restrict__ p,
                                                float* __restrict__ zt) {
    size_t base = (size_t)blockIdx.x * 2048;
    for (int n = threadIdx.x; n < 2048; n += 512)
        zt[base + n] = y[base + p[base + n]];
}

__device__ __forceinline__ void rowpack_body(const float* __restrict__ in,
                                             unsigned char* __restrict__ out,
                                             float* __restrict__ sc,
                                             int K, int r, int tid) {
    __shared__ float red[256];
    const float* row = in + (size_t)r * K;
    float m = 0.f;
    for (int k = tid; k < K; k += 256) m = fmaxf(m, fabsf(row[k]));
    red[tid] = m;
    __syncthreads();
    for (int st = 128; st > 0; st >>= 1) {
        if (tid < st) red[tid] = fmaxf(red[tid], red[tid + st]);
        __syncthreads();
    }
    float rmax = fmaxf(red[0], 1e-20f);
    float s = rmax / 127.f, inv = 127.f / rmax;
    if (tid == 0) sc[r] = s;
    int NC = K >> 6;
    for (int k0 = tid * 4; k0 < K; k0 += 1024) {
        float v[4];
#pragma unroll
        for (int j = 0; j < 4; j++) v[j] = row[k0 + j];
        pack_store4(out, NC, r, k0, v, s, inv);
    }
}

// all four weight packs in one launch; block = one row
__global__ __launch_bounds__(256) void packW_k(const float* __restrict__ sw1, unsigned char* __restrict__ o1, float* sc1,
                                               const float* __restrict__ sw2, unsigned char* __restrict__ o2, float* sc2,
                                               const float* __restrict__ fw1, unsigned char* __restrict__ o3, float* sc3,
                                               const float* __restrict__ fw2, unsigned char* __restrict__ o4, float* sc4) {
    int b = blockIdx.x, t = threadIdx.x;
    if (b < 8192)        rowpack_body(sw1, o1, sc1, N_,  b,         t);
    else if (b < 10240)  rowpack_body(sw2, o2, sc2, HS_, b - 8192,  t);
    else if (b < 14336)  rowpack_body(fw1, o3, sc3, F_,  b - 10240, t);
    else                 rowpack_body(fw2, o4, sc4, HF_, b - 14336, t);
}

__global__ __launch_bounds__(256) void packZ_k(const float* __restrict__ in,
                                               unsigned char* __restrict__ out,
                                               float* __restrict__ sc) {
    rowpack_body(in, out, sc, F_, blockIdx.x, threadIdx.x);
}

// ---------------------------------------------------------------------------
// int8 dual-quant IMMA GEMM. CTA 128x128, 512 thr, 16 warps, warp tile 32x32.
// chunk = 64 K-elems (A 16KB + B 16KB). 5-stage cp.async.bulk pipeline.
// out = sa*sb*(P11 + (P12+P21)/256) + bias, per element.
// MODE 0: relu -> int8 dual-quant packed (fixed out scale).
// MODE 1: +skip fp32.  MODE 2: fp32.
// ---------------------------------------------------------------------------
#define S_ 5
#define STAGE_B 32768
#define GEMM_SMEM (1024 + S_ * STAGE_B)

template <int MODE>
__global__ __launch_bounds__(512, 1) void gemm_imma(
    const unsigned char* __restrict__ Ap, const unsigned char* __restrict__ Bp,
    const float* __restrict__ saA, float saC,
    const float* __restrict__ sbB,
    const float* __restrict__ bias, const float* __restrict__ Skip,
    float* __restrict__ Cf, unsigned char* __restrict__ Cp,
    float out_s, float out_inv,
    int M, int Ntot, int K) {
    extern __shared__ __align__(1024) unsigned char smem_raw[];
    const uint32_t sb = smem_u32(smem_raw);
    const int tid = threadIdx.x;
    const int lane = tid & 31, wid = tid >> 5;
    const int wm = wid & 3, wn = wid >> 2;         // 4 x 4 warp grid, warp 32(M)x32(N)
    const int NC = K >> 6;
    const int m0 = blockIdx.y * 128, n0 = blockIdx.x * 128;

    const uint32_t FULL0 = sb;            // full[s] at sb+16s, free[s] at sb+16s+8
    const uint32_t DATA  = sb + 1024;

    if (tid == 0) {
        for (int s = 0; s < S_; s++) {
            mbar_init(FULL0 + 16 * s, 1);
            mbar_init(FULL0 + 16 * s + 8, 512);
        }
        asm volatile("fence.proxy.async.shared::cta;" ::: "memory");
    }
    __syncthreads();

    const unsigned char* Atile = Ap + (size_t)blockIdx.y * NC * 16384;
    const unsigned char* Btile = Bp + (size_t)blockIdx.x * NC * 16384;

    if (tid == 0) {
#pragma unroll
        for (int s = 0; s < S_ - 1; s++) {
            if (s < NC) {
                uint32_t st = DATA + (uint32_t)s * STAGE_B;
                mbar_expect_tx(FULL0 + 16 * s, STAGE_B);
                bulk_cp(st,          Atile + (size_t)s * 16384, 16384u, FULL0 + 16 * s);
                bulk_cp(st + 16384u, Btile + (size_t)s * 16384, 16384u, FULL0 + 16 * s);
            }
        }
    }

    int acc1[2][4][4], acc2[2][4][4];
#pragma unroll
    for (int a = 0; a < 2; a++)
#pragma unroll
        for (int b = 0; b < 4; b++)
#pragma unroll
            for (int c = 0; c < 4; c++) { acc1[a][b][c] = 0; acc2[a][b][c] = 0; }

    const int lr = lane & 15;
    const int lh = (lane >> 4) << 4;

    for (int kc = 0; kc < NC; kc++) {
        const int s = kc % S_;
        if (tid == 0) {
            int kp = kc + S_ - 1;
            if (kp < NC) {
                int sp = kp % S_;
                if (kp >= S_) mbar_wait(FULL0 + 16 * sp + 8, ((kp / S_) - 1) & 1);
                uint32_t st = DATA + (uint32_t)sp * STAGE_B;
                mbar_expect_tx(FULL0 + 16 * sp, STAGE_B);
                bulk_cp(st,          Atile + (size_t)kp * 16384, 16384u, FULL0 + 16 * sp);
                bulk_cp(st + 16384u, Btile + (size_t)kp * 16384, 16384u, FULL0 + 16 * sp);
            }
        }
        mbar_wait(FULL0 + 16 * s, (kc / S_) & 1);

        const uint32_t Ab = DATA + (uint32_t)s * STAGE_B;
        const uint32_t Bb = Ab + 16384u;

#pragma unroll
        for (int ks = 0; ks < 2; ks++) {
            uint32_t a[2][4], b1[2][4], b2[2][4];
            // q1 of A
#pragma unroll
            for (int mt = 0; mt < 2; mt++) {
                int row = wm * 32 + mt * 16 + lr;
                ldm_x4(a[mt], Ab + row * 128 + ((ks * 32 + lh) ^ ((row & 7) << 4)));
            }
            // q1 of B
#pragma unroll
            for (int nq = 0; nq < 2; nq++) {
                int row = wn * 32 + nq * 16 + lr;
                ldm_x4(b1[nq], Bb + row * 128 + ((ks * 32 + lh) ^ ((row & 7) << 4)));
            }
            // P11 -> acc1
#pragma unroll
            for (int mt = 0; mt < 2; mt++)
#pragma unroll
                for (int nq = 0; nq < 2; nq++) {
                    mma_s8(acc1[mt][2 * nq],     a[mt], b1[nq][0], b1[nq][2]);
                    mma_s8(acc1[mt][2 * nq + 1], a[mt], b1[nq][1], b1[nq][3]);
                }
            // q2 of B
#pragma unroll
            for (int nq = 0; nq < 2; nq++) {
                int row = wn * 32 + nq * 16 + lr;
                ldm_x4(b2[nq], Bb + row * 128 + ((64 + ks * 32 + lh) ^ ((row & 7) << 4)));
            }
            // P12 = q1A*q2B -> acc2
#pragma unroll
            for (int mt = 0; mt < 2; mt++)
#pragma unroll
                for (int nq = 0; nq < 2; nq++) {
                    mma_s8(acc2[mt][2 * nq],     a[mt], b2[nq][0], b2[nq][2]);
                    mma_s8(acc2[mt][2 * nq + 1], a[mt], b2[nq][1], b2[nq][3]);
                }
            // q2 of A (overwrite)
#pragma unroll
            for (int mt = 0; mt < 2; mt++) {
                int row = wm * 32 + mt * 16 + lr;
                ldm_x4(a[mt], Ab + row * 128 + ((64 + ks * 32 + lh) ^ ((row & 7) << 4)));
            }
            // P21 = q2A*q1B -> acc2
#pragma unroll
            for (int mt = 0; mt < 2; mt++)
#pragma unroll
                for (int nq = 0; nq < 2; nq++) {
                    mma_s8(acc2[mt][2 * nq],     a[mt], b1[nq][0], b1[nq][2]);
                    mma_s8(acc2[mt][2 * nq + 1], a[mt], b1[nq][1], b1[nq][3]);
                }
        }
        mbar_arrive(FULL0 + 16 * s + 8);
    }

    // ---- epilogue ----
    const int NCo = Ntot >> 6;
#pragma unroll
    for (int mt = 0; mt < 2; mt++) {
        int r0 = m0 + wm * 32 + mt * 16 + (lane >> 2);
        int r1 = r0 + 8;
        float sa0 = saA ? saA[r0] : saC;
        float sa1 = saA ? saA[r1] : saC;
#pragma unroll
        for (int nf = 0; nf < 4; nf++) {
            int c = n0 + wn * 32 + nf * 8 + (lane & 3) * 2;
            float sb0 = sbB[c], sb1 = sbB[c + 1];
            float bb0 = bias[c], bb1 = bias[c + 1];
            float f0 = (float)acc1[mt][nf][0] + (float)acc2[mt][nf][0] * (1.f / 256.f);
            float f1 = (float)acc1[mt][nf][1] + (float)acc2[mt][nf][1] * (1.f / 256.f);
            float f2 = (float)acc1[mt][nf][2] + (float)acc2[mt][nf][2] * (1.f / 256.f);
            float f3 = (float)acc1[mt][nf][3] + (float)acc2[mt][nf][3] * (1.f / 256.f);
            float v00 = f0 * sa0 * sb0 + bb0, v01 = f1 * sa0 * sb1 + bb1;
            float v10 = f2 * sa1 * sb0 + bb0, v11 = f3 * sa1 * sb1 + bb1;
            if (MODE == 0) {
                v00 = fmaxf(v00, 0.f); v01 = fmaxf(v01, 0.f);
                v10 = fmaxf(v10, 0.f); v11 = fmaxf(v11, 0.f);
                int j = c & 63;
#pragma unroll
                for (int rr = 0; rr < 2; rr++) {
                    int r = rr ? r1 : r0;
                    float va = rr ? v10 : v00, vb = rr ? v11 : v01;
                    int q1a, q2a, q1b, q2b;
                    quant1(va, out_s, out_inv, q1a, q2a);
                    quant1(vb, out_s, out_inv, q1b, q2b);
                    size_t tb = (((size_t)(r >> 7) * NCo + (c >> 6)) * 128 + (r & 127)) * 128;
                    int swz = (r & 7) << 4;
                    *(unsigned short*)(Cp + tb + (j ^ swz)) =
                        (unsigned short)((q1a & 0xff) | ((q1b & 0xff) << 8));
                    *(unsigned short*)(Cp + tb + ((j + 64) ^ swz)) =
                        (unsigned short)((q2a & 0xff) | ((q2b & 0xff) << 8));
                }
            } else if (MODE == 1) {
                const float2 s0 = *(const float2*)(Skip + (size_t)r0 * Ntot + c);
                const float2 s1 = *(const float2*)(Skip + (size_t)r1 * Ntot + c);
                *(float2*)(Cf + (size_t)r0 * Ntot + c) = make_float2(v00 + s0.x, v01 + s0.y);
                *(float2*)(Cf + (size_t)r1 * Ntot + c) = make_float2(v10 + s1.x, v11 + s1.y);
            } else {
                *(float2*)(Cf + (size_t)r0 * Ntot + c) = make_float2(v00, v01);
                *(float2*)(Cf + (size_t)r1 * Ntot + c) = make_float2(v10, v11);
            }
        }
    }
}

// ---------------------------------------------------------------------------
extern "C" void kernel_launch(void* const* d_in, const int* in_sizes, int n_in,
                              void* d_out, int out_size) {
    const float* x   = (const float*)d_in[0];
    const float* sw1 = (const float*)d_in[1];
    const float* sb1 = (const float*)d_in[2];
    const float* sw2 = (const float*)d_in[3];
    const float* sb2 = (const float*)d_in[4];
    const float* fw1 = (const float*)d_in[5];
    const float* fb1 = (const float*)d_in[6];
    const float* fw2 = (const float*)d_in[7];
    const float* fb2 = (const float*)d_in[8];
    float* out = (float*)d_out;

    unsigned char *xm, *xs, *xsp, *p, *h, *w1, *w2, *w3, *w4;
    float* sc;
    cudaGetSymbolAddress((void**)&xm,  g_xm);
    cudaGetSymbolAddress((void**)&xs,  g_xs);
    cudaGetSymbolAddress((void**)&xsp, g_xsp);
    cudaGetSymbolAddress((void**)&p,   g_p);
    cudaGetSymbolAddress((void**)&h,   g_h);
    cudaGetSymbolAddress((void**)&w1,  g_w1);
    cudaGetSymbolAddress((void**)&w2,  g_w2);
    cudaGetSymbolAddress((void**)&w3,  g_w3);
    cudaGetSymbolAddress((void**)&w4,  g_w4);
    cudaGetSymbolAddress((void**)&sc,  g_sc);

    cudaFuncSetAttribute((const void*)gemm_imma<0>, cudaFuncAttributeMaxDynamicSharedMemorySize, GEMM_SMEM);
    cudaFuncSetAttribute((const void*)gemm_imma<1>, cudaFuncAttributeMaxDynamicSharedMemorySize, GEMM_SMEM);
    cudaFuncSetAttribute((const void*)gemm_imma<2>, cudaFuncAttributeMaxDynamicSharedMemorySize, GEMM_SMEM);

    const int M1 = B_ * F_;   // 32768
    const int M2 = B_ * N_;   // 65536
    const float SH1 = 6.5f / 127.f, SH1I = 127.f / 6.5f;   // h  = relu(~N(0,1))
    const float SH2 = 8.0f / 127.f, SH2I = 127.f / 8.0f;   // h2 = relu(~N(0,1.3))

    // launch order keeps gemm1 at my index 3 (ncu -s 5 with 2 hidden launches)
    transpose_k<<<dim3(F_ / 32, N_ / 32, B_), dim3(32, 8)>>>(x, (float*)xm, N_, F_);    // 0
    sort_k<<<M1, 512>>>((const float*)xm, (float*)xs, xsp, sc + SC_XS, (int*)p);        // 1
    packW_k<<<15360, 256>>>(sw1, w1, sc + SC_W1, sw2, w2, sc + SC_W2,                   // 2
                            fw1, w3, sc + SC_W3, fw2, w4, sc + SC_W4);

    // 3) h = relu(xs @ sw1^T + sb1) -> int8 packed     <== ncu target
    gemm_imma<0><<<dim3(HS_ / 128, M1 / 128), 512, GEMM_SMEM>>>(                        // 3
        xsp, w1, sc + SC_XS, 0.f, sc + SC_W1, sb1, nullptr, nullptr, h, SH1, SH1I,
        M1, HS_, N_);

    // 4) y = h @ sw2^T + sb2 + xs -> fp32 (into xm)
    gemm_imma<1><<<dim3(N_ / 128, M1 / 128), 512, GEMM_SMEM>>>(
        h, w2, nullptr, SH1, sc + SC_W2, sb2, (const float*)xs, (float*)xm, nullptr,
        0.f, 0.f, M1, N_, HS_);

    // 5) zt = gather(y, p) (into xsp as fp32)
    gather_k<<<M1, 512>>>((const float*)xm, (const int*)p, (float*)xsp);

    // 6) z[b,n,f] = zt[b,f,n] (into xs)
    transpose_k<<<dim3(N_ / 32, F_ / 32, B_), dim3(32, 8)>>>((const float*)xsp, (float*)xs, F_, N_);

    // 7) pack z rows -> int8 packed (into xm) + per-row scales
    packZ_k<<<M2, 256>>>((const float*)xs, xm, sc + SC_Z);

    // 8) h2 = relu(z @ fw1^T + fb1) -> int8 packed (into h)
    gemm_imma<0><<<dim3(HF_ / 128, M2 / 128), 512, GEMM_SMEM>>>(
        xm, w3, sc + SC_Z, 0.f, sc + SC_W3, fb1, nullptr, nullptr, h, SH2, SH2I,
        M2, HF_, F_);

    // 9) out = h2 @ fw2^T + fb2 -> fp32
    gemm_imma<2><<<dim3(OUT_ / 128, M2 / 128), 512, GEMM_SMEM>>>(
        h, w4, nullptr, SH2, sc + SC_W4, fb2, nullptr, out, nullptr,
        0.f, 0.f, M2, OUT_, HF_);
}

// round 12
// speedup vs baseline: 3.8410x; 3.8410x over previous
#include <cuda_runtime.h>
#include <cuda_fp16.h>
#include <cstdint>

#define B_   32
#define N_   2048
#define F_   1024
#define OUT_ 1024
#define HS_  8192
#define HF_  4096

// ---------------------------------------------------------------------------
// Scratch (__device__ globals; allocation-free rule). ~2.25 GB.
// ---------------------------------------------------------------------------
__device__ __align__(1024) unsigned char g_xm [268435456];   // xm fp32 -> y fp32 -> z packed
__device__ __align__(1024) unsigned char g_xs [268435456];   // xs fp32 -> z fp32
__device__ __align__(1024) unsigned char g_xsp[268435456];   // xs packed-tiled -> zt fp32
__device__ __align__(1024) unsigned char g_p  [268435456];   // argsort indices (int)
__device__ __align__(1024) unsigned char g_h  [1073741824];  // h packed-tiled -> h2 packed-tiled
__device__ __align__(1024) unsigned char g_w1 [67108864];
__device__ __align__(1024) unsigned char g_w2 [67108864];
__device__ __align__(1024) unsigned char g_w3 [16777216];
__device__ __align__(1024) unsigned char g_w4 [16777216];

// ---------------------------------------------------------------------------
// PTX helpers (plain sm_90/sm_80 ISA — no 'a'-suffix features)
// ---------------------------------------------------------------------------
__device__ __forceinline__ uint32_t smem_u32(const void* p) {
    uint32_t a;
    asm("{ .reg .u64 t; cvta.to.shared.u64 t, %1; cvt.u32.u64 %0, t; }" : "=r"(a) : "l"(p));
    return a;
}
__device__ __forceinline__ void mbar_init(uint32_t m, uint32_t cnt) {
    asm volatile("mbarrier.init.shared.b64 [%0], %1;" :: "r"(m), "r"(cnt) : "memory");
}
__device__ __forceinline__ void mbar_wait(uint32_t m, uint32_t parity) {
    uint32_t done = 0;
    while (!done) {
        asm volatile(
            "{\n\t.reg .pred p;\n\t"
            "mbarrier.try_wait.parity.acquire.cta.shared::cta.b64 p, [%1], %2, 0x989680;\n\t"
            "selp.b32 %0, 1, 0, p;\n\t}"
            : "=r"(done) : "r"(m), "r"(parity) : "memory");
    }
}
__device__ __forceinline__ void mbar_arrive(uint32_t m) {
    asm volatile("mbarrier.arrive.shared.b64 _, [%0];" :: "r"(m) : "memory");
}
__device__ __forceinline__ void mbar_expect_tx(uint32_t m, uint32_t bytes) {
    asm volatile("mbarrier.arrive.expect_tx.shared.b64 _, [%0], %1;" :: "r"(m), "r"(bytes) : "memory");
}
__device__ __forceinline__ void bulk_cp(uint32_t dst, const void* src, uint32_t bytes, uint32_t mbar) {
    asm volatile("cp.async.bulk.shared::cta.global.mbarrier::complete_tx::bytes [%0], [%1], %2, [%3];"
                 :: "r"(dst), "l"(src), "r"(bytes), "r"(mbar) : "memory");
}
__device__ __forceinline__ void ldm_x4(uint32_t* r, uint32_t addr) {
    asm volatile("ldmatrix.sync.aligned.m8n8.x4.shared.b16 {%0,%1,%2,%3}, [%4];"
                 : "=r"(r[0]), "=r"(r[1]), "=r"(r[2]), "=r"(r[3]) : "r"(addr));
}
__device__ __forceinline__ void mma_f16(float* d, const uint32_t* a, uint32_t b0, uint32_t b1) {
    asm volatile("mma.sync.aligned.m16n8k16.row.col.f32.f16.f16.f32 "
                 "{%0,%1,%2,%3}, {%4,%5,%6,%7}, {%8,%9}, {%0,%1,%2,%3};"
                 : "+f"(d[0]), "+f"(d[1]), "+f"(d[2]), "+f"(d[3])
                 : "r"(a[0]), "r"(a[1]), "r"(a[2]), "r"(a[3]), "r"(b0), "r"(b1));
}

// ---------------------------------------------------------------------------
// Packed-tiled operand layout: rows grouped by 128 (tile), K by 32 (chunk).
// Tile (t, kc) = 16KB contiguous: 128 rows x 128B, row = [hi32|lo32] fp16
// groups, byte offset pre-swizzled with o ^ ((row&7)<<4).
// hi = RN fp16 of v (residual <= 2^-12 |v|); lo = fp16 of residual.
// ---------------------------------------------------------------------------
__device__ __forceinline__ void packed_store(unsigned char* base, int NC, int r, int k,
                                             float v0, float v1) {
    size_t tb = (((size_t)(r >> 7) * NC + (k >> 5)) * 128 + (r & 127)) * 128;
    int j2 = (k & 31) * 2;
    int swz = (r & 7) << 4;
    __half h0 = __float2half_rn(v0), h1 = __float2half_rn(v1);
    float l0 = v0 - __half2float(h0), l1 = v1 - __half2float(h1);
    __half L0 = __float2half_rn(l0), L1 = __float2half_rn(l1);
    uint32_t hb = ((uint32_t)__half_as_ushort(h1) << 16) | __half_as_ushort(h0);
    uint32_t lb = ((uint32_t)__half_as_ushort(L1) << 16) | __half_as_ushort(L0);
    *(uint32_t*)(base + tb + (j2 ^ swz)) = hb;
    *(uint32_t*)(base + tb + ((j2 + 64) ^ swz)) = lb;
}

// ---------------------------------------------------------------------------
// transpose / sort / gather / pack
// ---------------------------------------------------------------------------
__global__ void transpose_k(const float* __restrict__ src, float* __restrict__ dst,
                            int R, int C) {
    __shared__ float tile[32][33];
    size_t bo = (size_t)blockIdx.z * R * C;
    int r0 = blockIdx.y * 32, c0 = blockIdx.x * 32;
    int tx = threadIdx.x, ty = threadIdx.y;
#pragma unroll
    for (int i = 0; i < 32; i += 8)
        tile[ty + i][tx] = src[bo + (size_t)(r0 + ty + i) * C + (c0 + tx)];
    __syncthreads();
#pragma unroll
    for (int i = 0; i < 32; i += 8)
        dst[bo + (size_t)(c0 + ty + i) * R + (r0 + tx)] = tile[tx][ty + i];
}

__global__ __launch_bounds__(512) void sort_k(const float* __restrict__ xm,
                                              float* __restrict__ xs,
                                              unsigned char* __restrict__ xsp,
                                              int* __restrict__ p) {
    __shared__ unsigned long long key[2048];
    __shared__ float val[2048];
    __shared__ int   rnk[2048];
    size_t base = (size_t)blockIdx.x * 2048;
    int tid = threadIdx.x;

    for (int i = tid; i < 2048; i += 512) {
        float v = xm[base + i];
        val[i] = v;
        unsigned u = __float_as_uint(v);
        u = (u & 0x80000000u) ? ~u : (u | 0x80000000u);
        key[i] = ((unsigned long long)u << 32) | (unsigned)i;
    }
    __syncthreads();

    for (int k2 = 2; k2 <= 2048; k2 <<= 1) {
        for (int j = k2 >> 1; j > 0; j >>= 1) {
            for (int i = tid; i < 2048; i += 512) {
                int l = i ^ j;
                if (l > i) {
                    unsigned long long a = key[i], b = key[l];
                    bool asc = ((i & k2) == 0);
                    if ((a > b) == asc) { key[i] = b; key[l] = a; }
                }
            }
            __syncthreads();
        }
    }

    for (int i = tid; i < 2048; i += 512) {
        int pi = (int)(unsigned)(key[i] & 0xffffffffu);
        p[base + i] = pi;
        rnk[pi] = i;
    }
    __syncthreads();
    int r = blockIdx.x;
    for (int i = 2 * tid; i < 2048; i += 1024) {
        float v0 = val[rnk[i]], v1 = val[rnk[i + 1]];
        xs[base + i] = v0;
        xs[base + i + 1] = v1;
        packed_store(xsp, 64, r, i, v0, v1);   // NC = 2048/32
    }
}

__global__ __launch_bounds__(512) void gather_k(const float* __restrict__ y,
                                                const int* __restrict__ p,
                                                float* __restrict__ zt) {
    size_t base = (size_t)blockIdx.x * 2048;
    for (int n = threadIdx.x; n < 2048; n += 512)
        zt[base + n] = y[base + p[base + n]];
}

__device__ __forceinline__ void pack_body(const float* __restrict__ in,
                                          unsigned char* __restrict__ out,
                                          int K, int bid, int tid) {
    size_t gid = (size_t)bid * 256 + tid;
    size_t r = gid / (unsigned)(K / 2);
    int k = (int)(gid - r * (unsigned)(K / 2)) * 2;
    const float* row = in + r * (size_t)K;
    packed_store(out, K / 32, (int)r, k, row[k], row[k + 1]);
}

__global__ __launch_bounds__(256) void pack_k(const float* __restrict__ in,
                                              unsigned char* __restrict__ out, int K) {
    pack_body(in, out, K, blockIdx.x, threadIdx.x);
}

// All four weight packs in ONE launch (keeps gemm1 at my launch index 3).
__global__ __launch_bounds__(256) void packW_k(const float* __restrict__ sw1, unsigned char* __restrict__ o1,
                                               const float* __restrict__ sw2, unsigned char* __restrict__ o2,
                                               const float* __restrict__ fw1, unsigned char* __restrict__ o3,
                                               const float* __restrict__ fw2, unsigned char* __restrict__ o4) {
    int b = blockIdx.x, t = threadIdx.x;
    if (b < 32768)       pack_body(sw1, o1, N_,  b,         t);
    else if (b < 65536)  pack_body(sw2, o2, HS_, b - 32768, t);
    else if (b < 73728)  pack_body(fw1, o3, F_,  b - 65536, t);
    else                 pack_body(fw2, o4, HF_, b - 73728, t);
}

// ---------------------------------------------------------------------------
// fp16 2-pass mma.sync GEMM: C = Ah*(Bh + Bl)  (A hi-only, B exact hi+lo).
// CTA tile 128x128, 256 thr, warp tile 32x64, 2 CTAs/SM, S_=3 stages.
// MODE 0: bias+relu -> packed-tiled. MODE 1: bias+skip fp32. MODE 2: bias fp32.
// ---------------------------------------------------------------------------
#define S_ 3
#define STAGE_B 32768
#define GEMM_SMEM (1024 + S_ * STAGE_B)

template <int MODE>
__global__ __launch_bounds__(256, 2) void gemm_mma(
    const unsigned char* __restrict__ Ap, const unsigned char* __restrict__ Bp,
    const float* __restrict__ bias, const float* __restrict__ Skip,
    float* __restrict__ Cf, unsigned char* __restrict__ Cp,
    int M, int Ntot, int K) {
    extern __shared__ __align__(1024) unsigned char smem_raw[];
    const uint32_t sb = smem_u32(smem_raw);
    const int tid = threadIdx.x;
    const int lane = tid & 31, wid = tid >> 5;
    const int wm = wid & 3, wn = wid >> 2;         // 4 x 2 warp grid (M x N)
    const int NC = K / 32;
    const int m0 = blockIdx.y * 128, n0 = blockIdx.x * 128;

    const uint32_t FULL0 = sb;            // full[s] at sb+16s, free[s] at sb+16s+8
    const uint32_t DATA  = sb + 1024;

    if (tid == 0) {
        for (int s = 0; s < S_; s++) {
            mbar_init(FULL0 + 16 * s, 1);
            mbar_init(FULL0 + 16 * s + 8, 256);
        }
        asm volatile("fence.proxy.async.shared::cta;" ::: "memory");
    }
    __syncthreads();

    const unsigned char* Atile = Ap + (size_t)blockIdx.y * NC * 16384;
    const unsigned char* Btile = Bp + (size_t)blockIdx.x * NC * 16384;

    if (tid == 0) {
#pragma unroll
        for (int s = 0; s < S_ - 1; s++) {
            uint32_t st = DATA + (uint32_t)s * STAGE_B;
            mbar_expect_tx(FULL0 + 16 * s, STAGE_B);
            bulk_cp(st,          Atile + (size_t)s * 16384, 16384u, FULL0 + 16 * s);
            bulk_cp(st + 16384u, Btile + (size_t)s * 16384, 16384u, FULL0 + 16 * s);
        }
    }

    float acc[2][8][4];
#pragma unroll
    for (int a = 0; a < 2; a++)
#pragma unroll
        for (int b = 0; b < 8; b++)
#pragma unroll
            for (int c = 0; c < 4; c++) acc[a][b][c] = 0.f;

    const int lr = lane & 15;
    const int lh = (lane >> 4) << 4;

    for (int kc = 0; kc < NC; kc++) {
        const int s = kc % S_;
        if (tid == 0) {
            int kp = kc + S_ - 1;
            if (kp < NC) {
                int sp = kp % S_;
                if (kp >= S_) mbar_wait(FULL0 + 16 * sp + 8, ((kp / S_) - 1) & 1);
                uint32_t st = DATA + (uint32_t)sp * STAGE_B;
                mbar_expect_tx(FULL0 + 16 * sp, STAGE_B);
                bulk_cp(st,          Atile + (size_t)kp * 16384, 16384u, FULL0 + 16 * sp);
                bulk_cp(st + 16384u, Btile + (size_t)kp * 16384, 16384u, FULL0 + 16 * sp);
            }
        }
        mbar_wait(FULL0 + 16 * s, (kc / S_) & 1);

        const uint32_t Ab = DATA + (uint32_t)s * STAGE_B;
        const uint32_t Bb = Ab + 16384u;

        uint32_t a[2][2][4];   // [ks][mt] : Ah only
        uint32_t bh[2][4][4];  // [ks][nq] : Bh
#pragma unroll
        for (int ks = 0; ks < 2; ks++)
#pragma unroll
            for (int mt = 0; mt < 2; mt++) {
                int row = wm * 32 + mt * 16 + lr;
                ldm_x4(a[ks][mt], Ab + row * 128 + ((ks * 32 + lh) ^ ((row & 7) << 4)));
            }
#pragma unroll
        for (int ks = 0; ks < 2; ks++)
#pragma unroll
            for (int nq = 0; nq < 4; nq++) {
                int row = wn * 64 + nq * 16 + lr;
                ldm_x4(bh[ks][nq], Bb + row * 128 + ((ks * 32 + lh) ^ ((row & 7) << 4)));
            }
        // pass 1: Ah * Bh
#pragma unroll
        for (int ks = 0; ks < 2; ks++)
#pragma unroll
            for (int mt = 0; mt < 2; mt++)
#pragma unroll
                for (int nq = 0; nq < 4; nq++) {
                    mma_f16(acc[mt][2 * nq],     a[ks][mt], bh[ks][nq][0], bh[ks][nq][2]);
                    mma_f16(acc[mt][2 * nq + 1], a[ks][mt], bh[ks][nq][1], bh[ks][nq][3]);
                }
        // pass 2: Ah * Bl
#pragma unroll
        for (int ks = 0; ks < 2; ks++) {
            uint32_t bl[4][4];
#pragma unroll
            for (int nq = 0; nq < 4; nq++) {
                int row = wn * 64 + nq * 16 + lr;
                ldm_x4(bl[nq], Bb + row * 128 + ((64 + ks * 32 + lh) ^ ((row & 7) << 4)));
            }
#pragma unroll
            for (int mt = 0; mt < 2; mt++)
#pragma unroll
                for (int nq = 0; nq < 4; nq++) {
                    mma_f16(acc[mt][2 * nq],     a[ks][mt], bl[nq][0], bl[nq][2]);
                    mma_f16(acc[mt][2 * nq + 1], a[ks][mt], bl[nq][1], bl[nq][3]);
                }
        }
        mbar_arrive(FULL0 + 16 * s + 8);
    }

    // ---- epilogue ----
    const int NCo = Ntot / 32;
#pragma unroll
    for (int mt = 0; mt < 2; mt++) {
        int r0 = m0 + wm * 32 + mt * 16 + (lane >> 2);
#pragma unroll
        for (int nf = 0; nf < 8; nf++) {
            int c = n0 + wn * 64 + nf * 8 + (lane & 3) * 2;
            float b0 = bias[c], b1v = bias[c + 1];
            float v00 = acc[mt][nf][0] + b0, v01 = acc[mt][nf][1] + b1v;
            float v10 = acc[mt][nf][2] + b0, v11 = acc[mt][nf][3] + b1v;
            int r1 = r0 + 8;
            if (MODE == 0) {
                packed_store(Cp, NCo, r0, c, fmaxf(v00, 0.f), fmaxf(v01, 0.f));
                packed_store(Cp, NCo, r1, c, fmaxf(v10, 0.f), fmaxf(v11, 0.f));
            } else if (MODE == 1) {
                const float2 s0 = *(const float2*)(Skip + (size_t)r0 * Ntot + c);
                const float2 s1 = *(const float2*)(Skip + (size_t)r1 * Ntot + c);
                *(float2*)(Cf + (size_t)r0 * Ntot + c) = make_float2(v00 + s0.x, v01 + s0.y);
                *(float2*)(Cf + (size_t)r1 * Ntot + c) = make_float2(v10 + s1.x, v11 + s1.y);
            } else {
                *(float2*)(Cf + (size_t)r0 * Ntot + c) = make_float2(v00, v01);
                *(float2*)(Cf + (size_t)r1 * Ntot + c) = make_float2(v10, v11);
            }
        }
    }
}

// ---------------------------------------------------------------------------
extern "C" void kernel_launch(void* const* d_in, const int* in_sizes, int n_in,
                              void* d_out, int out_size) {
    const float* x   = (const float*)d_in[0];
    const float* sw1 = (const float*)d_in[1];
    const float* sb1 = (const float*)d_in[2];
    const float* sw2 = (const float*)d_in[3];
    const float* sb2 = (const float*)d_in[4];
    const float* fw1 = (const float*)d_in[5];
    const float* fb1 = (const float*)d_in[6];
    const float* fw2 = (const float*)d_in[7];
    const float* fb2 = (const float*)d_in[8];
    float* out = (float*)d_out;

    unsigned char *xm, *xs, *xsp, *p, *h, *w1, *w2, *w3, *w4;
    cudaGetSymbolAddress((void**)&xm,  g_xm);
    cudaGetSymbolAddress((void**)&xs,  g_xs);
    cudaGetSymbolAddress((void**)&xsp, g_xsp);
    cudaGetSymbolAddress((void**)&p,   g_p);
    cudaGetSymbolAddress((void**)&h,   g_h);
    cudaGetSymbolAddress((void**)&w1,  g_w1);
    cudaGetSymbolAddress((void**)&w2,  g_w2);
    cudaGetSymbolAddress((void**)&w3,  g_w3);
    cudaGetSymbolAddress((void**)&w4,  g_w4);

    cudaFuncSetAttribute((const void*)gemm_mma<0>, cudaFuncAttributeMaxDynamicSharedMemorySize, GEMM_SMEM);
    cudaFuncSetAttribute((const void*)gemm_mma<1>, cudaFuncAttributeMaxDynamicSharedMemorySize, GEMM_SMEM);
    cudaFuncSetAttribute((const void*)gemm_mma<2>, cudaFuncAttributeMaxDynamicSharedMemorySize, GEMM_SMEM);

    const int M1 = B_ * F_;   // 32768
    const int M2 = B_ * N_;   // 65536

    // launch order keeps gemm1 at my index 3 (ncu -s 5 lands there with 2 hidden launches)
    transpose_k<<<dim3(F_ / 32, N_ / 32, B_), dim3(32, 8)>>>(x, (float*)xm, N_, F_);    // 0
    sort_k<<<M1, 512>>>((const float*)xm, (float*)xs, xsp, (int*)p);                    // 1
    packW_k<<<81920, 256>>>(sw1, w1, sw2, w2, fw1, w3, fw2, w4);                        // 2

    // 3) h = relu(xs @ sw1^T + sb1) -> packed-tiled    <== ncu target
    gemm_mma<0><<<dim3(HS_ / 128, M1 / 128), 256, GEMM_SMEM>>>(                         // 3
        xsp, w1, sb1, nullptr, nullptr, h, M1, HS_, N_);

    // 4) y = h @ sw2^T + sb2 + xs -> fp32 (into xm)
    gemm_mma<1><<<dim3(N_ / 128, M1 / 128), 256, GEMM_SMEM>>>(
        h, w2, sb2, (const float*)xs, (float*)xm, nullptr, M1, N_, HS_);

    // 5) zt = gather(y, p) (into xsp as fp32)
    gather_k<<<M1, 512>>>((const float*)xm, (const int*)p, (float*)xsp);

    // 6) z[b,n,f] = zt[b,f,n] (into xs)
    transpose_k<<<dim3(N_ / 32, F_ / 32, B_), dim3(32, 8)>>>((const float*)xsp, (float*)xs, F_, N_);

    // 6b) pack z -> tiled (into xm)
    pack_k<<<(int)((size_t)M2 * F_ / 512), 256>>>((const float*)xs, xm, F_);

    // 7) h2 = relu(z @ fw1^T + fb1) -> packed-tiled (into h)
    gemm_mma<0><<<dim3(HF_ / 128, M2 / 128), 256, GEMM_SMEM>>>(
        xm, w3, fb1, nullptr, nullptr, h, M2, HF_, F_);

    // 8) out = h2 @ fw2^T + fb2 -> fp32
    gemm_mma<2><<<dim3(OUT_ / 128, M2 / 128), 256, GEMM_SMEM>>>(
        h, w4, fb2, nullptr, out, nullptr, M2, OUT_, HF_);
}

// round 13
// speedup vs baseline: 5.8963x; 1.5351x over previous
#include <cuda_runtime.h>
#include <cuda_fp16.h>
#include <cstdint>

#define B_   32
#define N_   2048
#define F_   1024
#define OUT_ 1024
#define HS_  8192
#define HF_  4096

// ---------------------------------------------------------------------------
// Scratch (__device__ globals; allocation-free rule). ~2.25 GB.
// ---------------------------------------------------------------------------
__device__ __align__(1024) unsigned char g_xm [268435456];   // xm fp32 -> y fp32 -> z packed
__device__ __align__(1024) unsigned char g_xs [268435456];   // xs fp32 -> z fp32
__device__ __align__(1024) unsigned char g_xsp[268435456];   // xs packed-tiled -> zt fp32
__device__ __align__(1024) unsigned char g_p  [268435456];   // argsort indices (int)
__device__ __align__(1024) unsigned char g_h  [1073741824];  // h packed-tiled -> h2 packed-tiled
__device__ __align__(1024) unsigned char g_w1 [67108864];
__device__ __align__(1024) unsigned char g_w2 [67108864];
__device__ __align__(1024) unsigned char g_w3 [16777216];
__device__ __align__(1024) unsigned char g_w4 [16777216];

// ---------------------------------------------------------------------------
// PTX helpers (plain sm_90/sm_80 ISA — no 'a'-suffix features)
// ---------------------------------------------------------------------------
__device__ __forceinline__ uint32_t smem_u32(const void* p) {
    uint32_t a;
    asm("{ .reg .u64 t; cvta.to.shared.u64 t, %1; cvt.u32.u64 %0, t; }" : "=r"(a) : "l"(p));
    return a;
}
__device__ __forceinline__ void mbar_init(uint32_t m, uint32_t cnt) {
    asm volatile("mbarrier.init.shared.b64 [%0], %1;" :: "r"(m), "r"(cnt) : "memory");
}
__device__ __forceinline__ void mbar_wait(uint32_t m, uint32_t parity) {
    uint32_t done = 0;
    while (!done) {
        asm volatile(
            "{\n\t.reg .pred p;\n\t"
            "mbarrier.try_wait.parity.acquire.cta.shared::cta.b64 p, [%1], %2, 0x989680;\n\t"
            "selp.b32 %0, 1, 0, p;\n\t}"
            : "=r"(done) : "r"(m), "r"(parity) : "memory");
    }
}
__device__ __forceinline__ void mbar_arrive(uint32_t m) {
    asm volatile("mbarrier.arrive.shared.b64 _, [%0];" :: "r"(m) : "memory");
}
__device__ __forceinline__ void mbar_expect_tx(uint32_t m, uint32_t bytes) {
    asm volatile("mbarrier.arrive.expect_tx.shared.b64 _, [%0], %1;" :: "r"(m), "r"(bytes) : "memory");
}
__device__ __forceinline__ void bulk_cp(uint32_t dst, const void* src, uint32_t bytes, uint32_t mbar) {
    asm volatile("cp.async.bulk.shared::cta.global.mbarrier::complete_tx::bytes [%0], [%1], %2, [%3];"
                 :: "r"(dst), "l"(src), "r"(bytes), "r"(mbar) : "memory");
}
__device__ __forceinline__ void ldm_x4(uint32_t* r, uint32_t addr) {
    asm volatile("ldmatrix.sync.aligned.m8n8.x4.shared.b16 {%0,%1,%2,%3}, [%4];"
                 : "=r"(r[0]), "=r"(r[1]), "=r"(r[2]), "=r"(r[3]) : "r"(addr));
}
__device__ __forceinline__ void mma_f16(float* d, const uint32_t* a, uint32_t b0, uint32_t b1) {
    asm volatile("mma.sync.aligned.m16n8k16.row.col.f32.f16.f16.f32 "
                 "{%0,%1,%2,%3}, {%4,%5,%6,%7}, {%8,%9}, {%0,%1,%2,%3};"
                 : "+f"(d[0]), "+f"(d[1]), "+f"(d[2]), "+f"(d[3])
                 : "r"(a[0]), "r"(a[1]), "r"(a[2]), "r"(a[3]), "r"(b0), "r"(b1));
}

// ---------------------------------------------------------------------------
// Packed-tiled operand layout: rows grouped by 128 (tile), K by 32 (chunk).
// Tile (t, kc) = 16KB contiguous: 128 rows x 128B, row = [hi32|lo32] fp16
// groups, byte offset pre-swizzled with o ^ ((row&7)<<4).
// (Single-pass GEMM reads only the hi plane; lo is written for layout
// stability but never consumed.)
// ---------------------------------------------------------------------------
__device__ __forceinline__ void packed_store(unsigned char* base, int NC, int r, int k,
                                             float v0, float v1) {
    size_t tb = (((size_t)(r >> 7) * NC + (k >> 5)) * 128 + (r & 127)) * 128;
    int j2 = (k & 31) * 2;
    int swz = (r & 7) << 4;
    __half h0 = __float2half_rn(v0), h1 = __float2half_rn(v1);
    float l0 = v0 - __half2float(h0), l1 = v1 - __half2float(h1);
    __half L0 = __float2half_rn(l0), L1 = __float2half_rn(l1);
    uint32_t hb = ((uint32_t)__half_as_ushort(h1) << 16) | __half_as_ushort(h0);
    uint32_t lb = ((uint32_t)__half_as_ushort(L1) << 16) | __half_as_ushort(L0);
    *(uint32_t*)(base + tb + (j2 ^ swz)) = hb;
    *(uint32_t*)(base + tb + ((j2 + 64) ^ swz)) = lb;
}

// ---------------------------------------------------------------------------
// transpose / sort / gather / pack
// ---------------------------------------------------------------------------
__global__ void transpose_k(const float* __restrict__ src, float* __restrict__ dst,
                            int R, int C) {
    __shared__ float tile[32][33];
    size_t bo = (size_t)blockIdx.z * R * C;
    int r0 = blockIdx.y * 32, c0 = blockIdx.x * 32;
    int tx = threadIdx.x, ty = threadIdx.y;
#pragma unroll
    for (int i = 0; i < 32; i += 8)
        tile[ty + i][tx] = src[bo + (size_t)(r0 + ty + i) * C + (c0 + tx)];
    __syncthreads();
#pragma unroll
    for (int i = 0; i < 32; i += 8)
        dst[bo + (size_t)(c0 + ty + i) * R + (r0 + tx)] = tile[tx][ty + i];
}

__global__ __launch_bounds__(512) void sort_k(const float* __restrict__ xm,
                                              float* __restrict__ xs,
                                              unsigned char* __restrict__ xsp,
                                              int* __restrict__ p) {
    __shared__ unsigned long long key[2048];
    __shared__ float val[2048];
    __shared__ int   rnk[2048];
    size_t base = (size_t)blockIdx.x * 2048;
    int tid = threadIdx.x;

    for (int i = tid; i < 2048; i += 512) {
        float v = xm[base + i];
        val[i] = v;
        unsigned u = __float_as_uint(v);
        u = (u & 0x80000000u) ? ~u : (u | 0x80000000u);
        key[i] = ((unsigned long long)u << 32) | (unsigned)i;
    }
    __syncthreads();

    for (int k2 = 2; k2 <= 2048; k2 <<= 1) {
        for (int j = k2 >> 1; j > 0; j >>= 1) {
            for (int i = tid; i < 2048; i += 512) {
                int l = i ^ j;
                if (l > i) {
                    unsigned long long a = key[i], b = key[l];
                    bool asc = ((i & k2) == 0);
                    if ((a > b) == asc) { key[i] = b; key[l] = a; }
                }
            }
            __syncthreads();
        }
    }

    for (int i = tid; i < 2048; i += 512) {
        int pi = (int)(unsigned)(key[i] & 0xffffffffu);
        p[base + i] = pi;
        rnk[pi] = i;
    }
    __syncthreads();
    int r = blockIdx.x;
    for (int i = 2 * tid; i < 2048; i += 1024) {
        float v0 = val[rnk[i]], v1 = val[rnk[i + 1]];
        xs[base + i] = v0;
        xs[base + i + 1] = v1;
        packed_store(xsp, 64, r, i, v0, v1);   // NC = 2048/32
    }
}

__global__ __launch_bounds__(512) void gather_k(const float* __restrict__ y,
                                                const int* __restrict__ p,
                                                float* __restrict__ zt) {
    size_t base = (size_t)blockIdx.x * 2048;
    for (int n = threadIdx.x; n < 2048; n += 512)
        zt[base + n] = y[base + p[base + n]];
}

__device__ __forceinline__ void pack_body(const float* __restrict__ in,
                                          unsigned char* __restrict__ out,
                                          int K, int bid, int tid) {
    size_t gid = (size_t)bid * 256 + tid;
    size_t r = gid / (unsigned)(K / 2);
    int k = (int)(gid - r * (unsigned)(K / 2)) * 2;
    const float* row = in + r * (size_t)K;
    packed_store(out, K / 32, (int)r, k, row[k], row[k + 1]);
}

__global__ __launch_bounds__(256) void pack_k(const float* __restrict__ in,
                                              unsigned char* __restrict__ out, int K) {
    pack_body(in, out, K, blockIdx.x, threadIdx.x);
}

// All four weight packs in ONE launch (keeps gemm1 at my launch index 3).
__global__ __launch_bounds__(256) void packW_k(const float* __restrict__ sw1, unsigned char* __restrict__ o1,
                                               const float* __restrict__ sw2, unsigned char* __restrict__ o2,
                                               const float* __restrict__ fw1, unsigned char* __restrict__ o3,
                                               const float* __restrict__ fw2, unsigned char* __restrict__ o4) {
    int b = blockIdx.x, t = threadIdx.x;
    if (b < 32768)       pack_body(sw1, o1, N_,  b,         t);
    else if (b < 65536)  pack_body(sw2, o2, HS_, b - 32768, t);
    else if (b < 73728)  pack_body(fw1, o3, F_,  b - 65536, t);
    else                 pack_body(fw2, o4, HF_, b - 73728, t);
}

// ---------------------------------------------------------------------------
// fp16 single-pass mma.sync GEMM: C = Ah*Bh (both operands RN fp16 hi).
// CTA tile 128x128, 256 thr, warp tile 32x64, 2 CTAs/SM, S_=3 stages.
// MODE 0: bias+relu -> packed-tiled. MODE 1: bias+skip fp32. MODE 2: bias fp32.
// ---------------------------------------------------------------------------
#define S_ 3
#define STAGE_B 32768
#define GEMM_SMEM (1024 + S_ * STAGE_B)

template <int MODE>
__global__ __launch_bounds__(256, 2) void gemm_mma(
    const unsigned char* __restrict__ Ap, const unsigned char* __restrict__ Bp,
    const float* __restrict__ bias, const float* __restrict__ Skip,
    float* __restrict__ Cf, unsigned char* __restrict__ Cp,
    int M, int Ntot, int K) {
    extern __shared__ __align__(1024) unsigned char smem_raw[];
    const uint32_t sb = smem_u32(smem_raw);
    const int tid = threadIdx.x;
    const int lane = tid & 31, wid = tid >> 5;
    const int wm = wid & 3, wn = wid >> 2;         // 4 x 2 warp grid (M x N)
    const int NC = K / 32;
    const int m0 = blockIdx.y * 128, n0 = blockIdx.x * 128;

    const uint32_t FULL0 = sb;            // full[s] at sb+16s, free[s] at sb+16s+8
    const uint32_t DATA  = sb + 1024;

    if (tid == 0) {
        for (int s = 0; s < S_; s++) {
            mbar_init(FULL0 + 16 * s, 1);
            mbar_init(FULL0 + 16 * s + 8, 256);
        }
        asm volatile("fence.proxy.async.shared::cta;" ::: "memory");
    }
    __syncthreads();

    const unsigned char* Atile = Ap + (size_t)blockIdx.y * NC * 16384;
    const unsigned char* Btile = Bp + (size_t)blockIdx.x * NC * 16384;

    if (tid == 0) {
#pragma unroll
        for (int s = 0; s < S_ - 1; s++) {
            uint32_t st = DATA + (uint32_t)s * STAGE_B;
            mbar_expect_tx(FULL0 + 16 * s, STAGE_B);
            bulk_cp(st,          Atile + (size_t)s * 16384, 16384u, FULL0 + 16 * s);
            bulk_cp(st + 16384u, Btile + (size_t)s * 16384, 16384u, FULL0 + 16 * s);
        }
    }

    float acc[2][8][4];
#pragma unroll
    for (int a = 0; a < 2; a++)
#pragma unroll
        for (int b = 0; b < 8; b++)
#pragma unroll
            for (int c = 0; c < 4; c++) acc[a][b][c] = 0.f;

    const int lr = lane & 15;
    const int lh = (lane >> 4) << 4;

    for (int kc = 0; kc < NC; kc++) {
        const int s = kc % S_;
        if (tid == 0) {
            int kp = kc + S_ - 1;
            if (kp < NC) {
                int sp = kp % S_;
                if (kp >= S_) mbar_wait(FULL0 + 16 * sp + 8, ((kp / S_) - 1) & 1);
                uint32_t st = DATA + (uint32_t)sp * STAGE_B;
                mbar_expect_tx(FULL0 + 16 * sp, STAGE_B);
                bulk_cp(st,          Atile + (size_t)kp * 16384, 16384u, FULL0 + 16 * sp);
                bulk_cp(st + 16384u, Btile + (size_t)kp * 16384, 16384u, FULL0 + 16 * sp);
            }
        }
        mbar_wait(FULL0 + 16 * s, (kc / S_) & 1);

        const uint32_t Ab = DATA + (uint32_t)s * STAGE_B;
        const uint32_t Bb = Ab + 16384u;

        uint32_t a[2][2][4];   // [ks][mt] : Ah
        uint32_t bh[2][4][4];  // [ks][nq] : Bh
#pragma unroll
        for (int ks = 0; ks < 2; ks++)
#pragma unroll
            for (int mt = 0; mt < 2; mt++) {
                int row = wm * 32 + mt * 16 + lr;
                ldm_x4(a[ks][mt], Ab + row * 128 + ((ks * 32 + lh) ^ ((row & 7) << 4)));
            }
#pragma unroll
        for (int ks = 0; ks < 2; ks++)
#pragma unroll
            for (int nq = 0; nq < 4; nq++) {
                int row = wn * 64 + nq * 16 + lr;
                ldm_x4(bh[ks][nq], Bb + row * 128 + ((ks * 32 + lh) ^ ((row & 7) << 4)));
            }
        // single pass: Ah * Bh
#pragma unroll
        for (int ks = 0; ks < 2; ks++)
#pragma unroll
            for (int mt = 0; mt < 2; mt++)
#pragma unroll
                for (int nq = 0; nq < 4; nq++) {
                    mma_f16(acc[mt][2 * nq],     a[ks][mt], bh[ks][nq][0], bh[ks][nq][2]);
                    mma_f16(acc[mt][2 * nq + 1], a[ks][mt], bh[ks][nq][1], bh[ks][nq][3]);
                }
        mbar_arrive(FULL0 + 16 * s + 8);
    }

    // ---- epilogue ----
    const int NCo = Ntot / 32;
#pragma unroll
    for (int mt = 0; mt < 2; mt++) {
        int r0 = m0 + wm * 32 + mt * 16 + (lane >> 2);
#pragma unroll
        for (int nf = 0; nf < 8; nf++) {
            int c = n0 + wn * 64 + nf * 8 + (lane & 3) * 2;
            float b0 = bias[c], b1v = bias[c + 1];
            float v00 = acc[mt][nf][0] + b0, v01 = acc[mt][nf][1] + b1v;
            float v10 = acc[mt][nf][2] + b0, v11 = acc[mt][nf][3] + b1v;
            int r1 = r0 + 8;
            if (MODE == 0) {
                packed_store(Cp, NCo, r0, c, fmaxf(v00, 0.f), fmaxf(v01, 0.f));
                packed_store(Cp, NCo, r1, c, fmaxf(v10, 0.f), fmaxf(v11, 0.f));
            } else if (MODE == 1) {
                const float2 s0 = *(const float2*)(Skip + (size_t)r0 * Ntot + c);
                const float2 s1 = *(const float2*)(Skip + (size_t)r1 * Ntot + c);
                *(float2*)(Cf + (size_t)r0 * Ntot + c) = make_float2(v00 + s0.x, v01 + s0.y);
                *(float2*)(Cf + (size_t)r1 * Ntot + c) = make_float2(v10 + s1.x, v11 + s1.y);
            } else {
                *(float2*)(Cf + (size_t)r0 * Ntot + c) = make_float2(v00, v01);
                *(float2*)(Cf + (size_t)r1 * Ntot + c) = make_float2(v10, v11);
            }
        }
    }
}

// ---------------------------------------------------------------------------
extern "C" void kernel_launch(void* const* d_in, const int* in_sizes, int n_in,
                              void* d_out, int out_size) {
    const float* x   = (const float*)d_in[0];
    const float* sw1 = (const float*)d_in[1];
    const float* sb1 = (const float*)d_in[2];
    const float* sw2 = (const float*)d_in[3];
    const float* sb2 = (const float*)d_in[4];
    const float* fw1 = (const float*)d_in[5];
    const float* fb1 = (const float*)d_in[6];
    const float* fw2 = (const float*)d_in[7];
    const float* fb2 = (const float*)d_in[8];
    float* out = (float*)d_out;

    unsigned char *xm, *xs, *xsp, *p, *h, *w1, *w2, *w3, *w4;
    cudaGetSymbolAddress((void**)&xm,  g_xm);
    cudaGetSymbolAddress((void**)&xs,  g_xs);
    cudaGetSymbolAddress((void**)&xsp, g_xsp);
    cudaGetSymbolAddress((void**)&p,   g_p);
    cudaGetSymbolAddress((void**)&h,   g_h);
    cudaGetSymbolAddress((void**)&w1,  g_w1);
    cudaGetSymbolAddress((void**)&w2,  g_w2);
    cudaGetSymbolAddress((void**)&w3,  g_w3);
    cudaGetSymbolAddress((void**)&w4,  g_w4);

    cudaFuncSetAttribute((const void*)gemm_mma<0>, cudaFuncAttributeMaxDynamicSharedMemorySize, GEMM_SMEM);
    cudaFuncSetAttribute((const void*)gemm_mma<1>, cudaFuncAttributeMaxDynamicSharedMemorySize, GEMM_SMEM);
    cudaFuncSetAttribute((const void*)gemm_mma<2>, cudaFuncAttributeMaxDynamicSharedMemorySize, GEMM_SMEM);

    const int M1 = B_ * F_;   // 32768
    const int M2 = B_ * N_;   // 65536

    // launch order keeps gemm1 at my index 3 (ncu -s 5 lands there with 2 hidden launches)
    transpose_k<<<dim3(F_ / 32, N_ / 32, B_), dim3(32, 8)>>>(x, (float*)xm, N_, F_);    // 0
    sort_k<<<M1, 512>>>((const float*)xm, (float*)xs, xsp, (int*)p);                    // 1
    packW_k<<<81920, 256>>>(sw1, w1, sw2, w2, fw1, w3, fw2, w4);                        // 2

    // 3) h = relu(xs @ sw1^T + sb1) -> packed-tiled    <== ncu target
    gemm_mma<0><<<dim3(HS_ / 128, M1 / 128), 256, GEMM_SMEM>>>(                         // 3
        xsp, w1, sb1, nullptr, nullptr, h, M1, HS_, N_);

    // 4) y = h @ sw2^T + sb2 + xs -> fp32 (into xm)
    gemm_mma<1><<<dim3(N_ / 128, M1 / 128), 256, GEMM_SMEM>>>(
        h, w2, sb2, (const float*)xs, (float*)xm, nullptr, M1, N_, HS_);

    // 5) zt = gather(y, p) (into xsp as fp32)
    gather_k<<<M1, 512>>>((const float*)xm, (const int*)p, (float*)xsp);

    // 6) z[b,n,f] = zt[b,f,n] (into xs)
    transpose_k<<<dim3(N_ / 32, F_ / 32, B_), dim3(32, 8)>>>((const float*)xsp, (float*)xs, F_, N_);

    // 6b) pack z -> tiled (into xm)
    pack_k<<<(int)((size_t)M2 * F_ / 512), 256>>>((const float*)xs, xm, F_);

    // 7) h2 = relu(z @ fw1^T + fb1) -> packed-tiled (into h)
    gemm_mma<0><<<dim3(HF_ / 128, M2 / 128), 256, GEMM_SMEM>>>(
        xm, w3, fb1, nullptr, nullptr, h, M2, HF_, F_);

    // 8) out = h2 @ fw2^T + fb2 -> fp32
    gemm_mma<2><<<dim3(OUT_ / 128, M2 / 128), 256, GEMM_SMEM>>>(
        h, w4, fb2, nullptr, out, nullptr, M2, OUT_, HF_);
}

// round 15
// speedup vs baseline: 6.3228x; 1.0723x over previous
#include <cuda_runtime.h>
#include <cuda_fp16.h>
#include <cstdint>

#define B_   32
#define N_   2048
#define F_   1024
#define OUT_ 1024
#define HS_  8192
#define HF_  4096

// ---------------------------------------------------------------------------
// Scratch (__device__ globals; allocation-free rule).
// ---------------------------------------------------------------------------
__device__ __align__(1024) unsigned char g_xm [268435456];   // xm fp32 -> y fp32 -> z packed
__device__ __align__(1024) unsigned char g_xs [268435456];   // xs fp32 -> z fp32
__device__ __align__(1024) unsigned char g_xsp[268435456];   // xs packed-tiled -> zt fp32
__device__ __align__(1024) unsigned char g_p  [268435456];   // argsort indices (int)
__device__ __align__(1024) unsigned char g_h  [1073741824];  // h packed-tiled -> h2 packed-tiled
__device__ __align__(1024) unsigned char g_w1 [33554432];    // 8192x2048 fp16
__device__ __align__(1024) unsigned char g_w2 [33554432];    // 2048x8192 fp16
__device__ __align__(1024) unsigned char g_w3 [8388608];     // 4096x1024 fp16
__device__ __align__(1024) unsigned char g_w4 [8388608];     // 1024x4096 fp16

// ---------------------------------------------------------------------------
// PTX helpers (plain sm_90/sm_80 ISA — no 'a'-suffix features)
// ---------------------------------------------------------------------------
__device__ __forceinline__ uint32_t smem_u32(const void* p) {
    uint32_t a;
    asm("{ .reg .u64 t; cvta.to.shared.u64 t, %1; cvt.u32.u64 %0, t; }" : "=r"(a) : "l"(p));
    return a;
}
__device__ __forceinline__ void mbar_init(uint32_t m, uint32_t cnt) {
    asm volatile("mbarrier.init.shared.b64 [%0], %1;" :: "r"(m), "r"(cnt) : "memory");
}
__device__ __forceinline__ void mbar_wait(uint32_t m, uint32_t parity) {
    uint32_t done = 0;
    while (!done) {
        asm volatile(
            "{\n\t.reg .pred p;\n\t"
            "mbarrier.try_wait.parity.acquire.cta.shared::cta.b64 p, [%1], %2, 0x989680;\n\t"
            "selp.b32 %0, 1, 0, p;\n\t}"
            : "=r"(done) : "r"(m), "r"(parity) : "memory");
    }
}
__device__ __forceinline__ void mbar_arrive(uint32_t m) {
    asm volatile("mbarrier.arrive.shared.b64 _, [%0];" :: "r"(m) : "memory");
}
__device__ __forceinline__ void mbar_expect_tx(uint32_t m, uint32_t bytes) {
    asm volatile("mbarrier.arrive.expect_tx.shared.b64 _, [%0], %1;" :: "r"(m), "r"(bytes) : "memory");
}
__device__ __forceinline__ void bulk_cp(uint32_t dst, const void* src, uint32_t bytes, uint32_t mbar) {
    asm volatile("cp.async.bulk.shared::cta.global.mbarrier::complete_tx::bytes [%0], [%1], %2, [%3];"
                 :: "r"(dst), "l"(src), "r"(bytes), "r"(mbar) : "memory");
}
__device__ __forceinline__ void ldm_x4(uint32_t* r, uint32_t addr) {
    asm volatile("ldmatrix.sync.aligned.m8n8.x4.shared.b16 {%0,%1,%2,%3}, [%4];"
                 : "=r"(r[0]), "=r"(r[1]), "=r"(r[2]), "=r"(r[3]) : "r"(addr));
}
__device__ __forceinline__ void mma_f16(float* d, const uint32_t* a, uint32_t b0, uint32_t b1) {
    asm volatile("mma.sync.aligned.m16n8k16.row.col.f32.f16.f16.f32 "
                 "{%0,%1,%2,%3}, {%4,%5,%6,%7}, {%8,%9}, {%0,%1,%2,%3};"
                 : "+f"(d[0]), "+f"(d[1]), "+f"(d[2]), "+f"(d[3])
                 : "r"(a[0]), "r"(a[1]), "r"(a[2]), "r"(a[3]), "r"(b0), "r"(b1));
}

// ---------------------------------------------------------------------------
// Hi-only packed-tiled layout: rows in 128-groups, K in 64-groups.
// Tile (t, kc) = 16KB contiguous: 128 rows x 128B, row = 64 fp16 K-elems,
// byte offset pre-swizzled with o ^ ((row&7)<<4).
// ---------------------------------------------------------------------------
__device__ __forceinline__ void packed_store(unsigned char* base, int NC, int r, int k,
                                             float v0, float v1) {
    size_t tb = (((size_t)(r >> 7) * NC + (k >> 6)) * 128 + (r & 127)) * 128;
    int j2 = (k & 63) * 2;
    int swz = (r & 7) << 4;
    __half h0 = __float2half_rn(v0), h1 = __float2half_rn(v1);
    uint32_t hb = ((uint32_t)__half_as_ushort(h1) << 16) | __half_as_ushort(h0);
    *(uint32_t*)(base + tb + (j2 ^ swz)) = hb;
}

// ---------------------------------------------------------------------------
// transpose / sort / gather / pack
// ---------------------------------------------------------------------------
__global__ void transpose_k(const float* __restrict__ src, float* __restrict__ dst,
                            int R, int C) {
    __shared__ float tile[32][33];
    size_t bo = (size_t)blockIdx.z * R * C;
    int r0 = blockIdx.y * 32, c0 = blockIdx.x * 32;
    int tx = threadIdx.x, ty = threadIdx.y;
#pragma unroll
    for (int i = 0; i < 32; i += 8)
        tile[ty + i][tx] = src[bo + (size_t)(r0 + ty + i) * C + (c0 + tx)];
    __syncthreads();
#pragma unroll
    for (int i = 0; i < 32; i += 8)
        dst[bo + (size_t)(c0 + ty + i) * R + (r0 + tx)] = tile[tx][ty + i];
}

__global__ __launch_bounds__(512) void sort_k(const float* __restrict__ xm,
                                              float* __restrict__ xs,
                                              unsigned char* __restrict__ xsp,
                                              int* __restrict__ p) {
    __shared__ unsigned long long key[2048];
    __shared__ float val[2048];
    __shared__ int   rnk[2048];
    size_t base = (size_t)blockIdx.x * 2048;
    int tid = threadIdx.x;

    for (int i = tid; i < 2048; i += 512) {
        float v = xm[base + i];
        val[i] = v;
        unsigned u = __float_as_uint(v);
        u = (u & 0x80000000u) ? ~u : (u | 0x80000000u);
        key[i] = ((unsigned long long)u << 32) | (unsigned)i;
    }
    __syncthreads();

    for (int k2 = 2; k2 <= 2048; k2 <<= 1) {
        for (int j = k2 >> 1; j > 0; j >>= 1) {
            for (int i = tid; i < 2048; i += 512) {
                int l = i ^ j;
                if (l > i) {
                    unsigned long long a = key[i], b = key[l];
                    bool asc = ((i & k2) == 0);
                    if ((a > b) == asc) { key[i] = b; key[l] = a; }
                }
            }
            __syncthreads();
        }
    }

    for (int i = tid; i < 2048; i += 512) {
        int pi = (int)(unsigned)(key[i] & 0xffffffffu);
        p[base + i] = pi;
        rnk[pi] = i;
    }
    __syncthreads();
    int r = blockIdx.x;
    for (int i = 2 * tid; i < 2048; i += 1024) {
        float v0 = val[rnk[i]], v1 = val[rnk[i + 1]];
        xs[base + i] = v0;
        xs[base + i + 1] = v1;
        packed_store(xsp, 32, r, i, v0, v1);   // NC = 2048/64
    }
}

__global__ __launch_bounds__(512) void gather_k(const float* __restrict__ y,
                                                const int* __restrict__ p,
                                                float* __restrict__ zt) {
    size_t base = (size_t)blockIdx.x * 2048;
    for (int n = threadIdx.x; n < 2048; n += 512)
        zt[base + n] = y[base + p[base + n]];
}

__device__ __forceinline__ void pack_body(const float* __restrict__ in,
                                          unsigned char* __restrict__ out,
                                          int K, int bid, int tid) {
    size_t gid = (size_t)bid * 256 + tid;
    size_t r = gid / (unsigned)(K / 2);
    int k = (int)(gid - r * (unsigned)(K / 2)) * 2;
    const float* row = in + r * (size_t)K;
    packed_store(out, K / 64, (int)r, k, row[k], row[k + 1]);
}

__global__ __launch_bounds__(256) void pack_k(const float* __restrict__ in,
                                              unsigned char* __restrict__ out, int K) {
    pack_body(in, out, K, blockIdx.x, threadIdx.x);
}

// All four weight packs in ONE launch (keeps gemm1 at my launch index 3).
__global__ __launch_bounds__(256) void packW_k(const float* __restrict__ sw1, unsigned char* __restrict__ o1,
                                               const float* __restrict__ sw2, unsigned char* __restrict__ o2,
                                               const float* __restrict__ fw1, unsigned char* __restrict__ o3,
                                               const float* __restrict__ fw2, unsigned char* __restrict__ o4) {
    int b = blockIdx.x, t = threadIdx.x;
    if (b < 32768)       pack_body(sw1, o1, N_,  b,         t);
    else if (b < 65536)  pack_body(sw2, o2, HS_, b - 32768, t);
    else if (b < 73728)  pack_body(fw1, o3, F_,  b - 65536, t);
    else                 pack_body(fw2, o4, HF_, b - 73728, t);
}

// ---------------------------------------------------------------------------
// fp16 single-pass mma.sync GEMM on hi-only layout (chunk = 64 K-elems).
// CTA tile 128x128, 256 thr, warp tile 32x64, 2 CTAs/SM, S_=3 stages.
// MODE 0: bias+relu -> packed-tiled. MODE 1: bias+skip fp32. MODE 2: bias fp32.
// ---------------------------------------------------------------------------
#define S_ 3
#define STAGE_B 32768
#define GEMM_SMEM (1024 + S_ * STAGE_B)

template <int MODE>
__global__ __launch_bounds__(256, 2) void gemm_mma(
    const unsigned char* __restrict__ Ap, const unsigned char* __restrict__ Bp,
    const float* __restrict__ bias, const float* __restrict__ Skip,
    float* __restrict__ Cf, unsigned char* __restrict__ Cp,
    int M, int Ntot, int K) {
    extern __shared__ __align__(1024) unsigned char smem_raw[];
    const uint32_t sb = smem_u32(smem_raw);
    const int tid = threadIdx.x;
    const int lane = tid & 31, wid = tid >> 5;
    const int wm = wid & 3, wn = wid >> 2;         // 4 x 2 warp grid (M x N)
    const int NC = K / 64;
    const int m0 = blockIdx.y * 128, n0 = blockIdx.x * 128;

    const uint32_t FULL0 = sb;            // full[s] at sb+16s, free[s] at sb+16s+8
    const uint32_t DATA  = sb + 1024;

    if (tid == 0) {
        for (int s = 0; s < S_; s++) {
            mbar_init(FULL0 + 16 * s, 1);
            mbar_init(FULL0 + 16 * s + 8, 256);
        }
        asm volatile("fence.proxy.async.shared::cta;" ::: "memory");
    }
    __syncthreads();

    const unsigned char* Atile = Ap + (size_t)blockIdx.y * NC * 16384;
    const unsigned char* Btile = Bp + (size_t)blockIdx.x * NC * 16384;

    if (tid == 0) {
#pragma unroll
        for (int s = 0; s < S_ - 1; s++) {
            if (s < NC) {
                uint32_t st = DATA + (uint32_t)s * STAGE_B;
                mbar_expect_tx(FULL0 + 16 * s, STAGE_B);
                bulk_cp(st,          Atile + (size_t)s * 16384, 16384u, FULL0 + 16 * s);
                bulk_cp(st + 16384u, Btile + (size_t)s * 16384, 16384u, FULL0 + 16 * s);
            }
        }
    }

    float acc[2][8][4];
#pragma unroll
    for (int a = 0; a < 2; a++)
#pragma unroll
        for (int b = 0; b < 8; b++)
#pragma unroll
            for (int c = 0; c < 4; c++) acc[a][b][c] = 0.f;

    const int lr = lane & 15;
    const int lh = (lane >> 4) << 4;

    for (int kc = 0; kc < NC; kc++) {
        const int s = kc % S_;
        if (tid == 0) {
            int kp = kc + S_ - 1;
            if (kp < NC) {
                int sp = kp % S_;
                if (kp >= S_) mbar_wait(FULL0 + 16 * sp + 8, ((kp / S_) - 1) & 1);
                uint32_t st = DATA + (uint32_t)sp * STAGE_B;
                mbar_expect_tx(FULL0 + 16 * sp, STAGE_B);
                bulk_cp(st,          Atile + (size_t)kp * 16384, 16384u, FULL0 + 16 * sp);
                bulk_cp(st + 16384u, Btile + (size_t)kp * 16384, 16384u, FULL0 + 16 * sp);
            }
        }
        mbar_wait(FULL0 + 16 * s, (kc / S_) & 1);

        const uint32_t Ab = DATA + (uint32_t)s * STAGE_B;
        const uint32_t Bb = Ab + 16384u;

        // 64 K-elems per chunk = two 32-elem halves (keeps register footprint)
#pragma unroll
        for (int half = 0; half < 2; half++) {
            const int off = half * 64;   // byte offset within 128B row
            uint32_t a[2][2][4];   // [ks][mt]
            uint32_t bh[2][4][4];  // [ks][nq]
#pragma unroll
            for (int ks = 0; ks < 2; ks++)
#pragma unroll
                for (int mt = 0; mt < 2; mt++) {
                    int row = wm * 32 + mt * 16 + lr;
                    ldm_x4(a[ks][mt], Ab + row * 128 + ((off + ks * 32 + lh) ^ ((row & 7) << 4)));
                }
#pragma unroll
            for (int ks = 0; ks < 2; ks++)
#pragma unroll
                for (int nq = 0; nq < 4; nq++) {
                    int row = wn * 64 + nq * 16 + lr;
                    ldm_x4(bh[ks][nq], Bb + row * 128 + ((off + ks * 32 + lh) ^ ((row & 7) << 4)));
                }
#pragma unroll
            for (int ks = 0; ks < 2; ks++)
#pragma unroll
                for (int mt = 0; mt < 2; mt++)
#pragma unroll
                    for (int nq = 0; nq < 4; nq++) {
                        mma_f16(acc[mt][2 * nq],     a[ks][mt], bh[ks][nq][0], bh[ks][nq][2]);
                        mma_f16(acc[mt][2 * nq + 1], a[ks][mt], bh[ks][nq][1], bh[ks][nq][3]);
                    }
        }
        mbar_arrive(FULL0 + 16 * s + 8);
    }

    // ---- epilogue ----
    const int NCo = Ntot / 64;
#pragma unroll
    for (int mt = 0; mt < 2; mt++) {
        int r0 = m0 + wm * 32 + mt * 16 + (lane >> 2);
#pragma unroll
        for (int nf = 0; nf < 8; nf++) {
            int c = n0 + wn * 64 + nf * 8 + (lane & 3) * 2;
            float b0 = bias[c], b1v = bias[c + 1];
            float v00 = acc[mt][nf][0] + b0, v01 = acc[mt][nf][1] + b1v;
            float v10 = acc[mt][nf][2] + b0, v11 = acc[mt][nf][3] + b1v;
            int r1 = r0 + 8;
            if (MODE == 0) {
                packed_store(Cp, NCo, r0, c, fmaxf(v00, 0.f), fmaxf(v01, 0.f));
                packed_store(Cp, NCo, r1, c, fmaxf(v10, 0.f), fmaxf(v11, 0.f));
            } else if (MODE == 1) {
                const float2 s0 = *(const float2*)(Skip + (size_t)r0 * Ntot + c);
                const float2 s1 = *(const float2*)(Skip + (size_t)r1 * Ntot + c);
                *(float2*)(Cf + (size_t)r0 * Ntot + c) = make_float2(v00 + s0.x, v01 + s0.y);
                *(float2*)(Cf + (size_t)r1 * Ntot + c) = make_float2(v10 + s1.x, v11 + s1.y);
            } else {
                *(float2*)(Cf + (size_t)r0 * Ntot + c) = make_float2(v00, v01);
                *(float2*)(Cf + (size_t)r1 * Ntot + c) = make_float2(v10, v11);
            }
        }
    }
}

// ---------------------------------------------------------------------------
extern "C" void kernel_launch(void* const* d_in, const int* in_sizes, int n_in,
                              void* d_out, int out_size) {
    const float* x   = (const float*)d_in[0];
    const float* sw1 = (const float*)d_in[1];
    const float* sb1 = (const float*)d_in[2];
    const float* sw2 = (const float*)d_in[3];
    const float* sb2 = (const float*)d_in[4];
    const float* fw1 = (const float*)d_in[5];
    const float* fb1 = (const float*)d_in[6];
    const float* fw2 = (const float*)d_in[7];
    const float* fb2 = (const float*)d_in[8];
    float* out = (float*)d_out;

    unsigned char *xm, *xs, *xsp, *p, *h, *w1, *w2, *w3, *w4;
    cudaGetSymbolAddress((void**)&xm,  g_xm);
    cudaGetSymbolAddress((void**)&xs,  g_xs);
    cudaGetSymbolAddress((void**)&xsp, g_xsp);
    cudaGetSymbolAddress((void**)&p,   g_p);
    cudaGetSymbolAddress((void**)&h,   g_h);
    cudaGetSymbolAddress((void**)&w1,  g_w1);
    cudaGetSymbolAddress((void**)&w2,  g_w2);
    cudaGetSymbolAddress((void**)&w3,  g_w3);
    cudaGetSymbolAddress((void**)&w4,  g_w4);

    cudaFuncSetAttribute((const void*)gemm_mma<0>, cudaFuncAttributeMaxDynamicSharedMemorySize, GEMM_SMEM);
    cudaFuncSetAttribute((const void*)gemm_mma<1>, cudaFuncAttributeMaxDynamicSharedMemorySize, GEMM_SMEM);
    cudaFuncSetAttribute((const void*)gemm_mma<2>, cudaFuncAttributeMaxDynamicSharedMemorySize, GEMM_SMEM);

    const int M1 = B_ * F_;   // 32768
    const int M2 = B_ * N_;   // 65536

    // launch order keeps gemm1 at my index 3 (ncu -s 5 lands there with 2 hidden launches)
    transpose_k<<<dim3(F_ / 32, N_ / 32, B_), dim3(32, 8)>>>(x, (float*)xm, N_, F_);    // 0
    sort_k<<<M1, 512>>>((const float*)xm, (float*)xs, xsp, (int*)p);                    // 1
    packW_k<<<81920, 256>>>(sw1, w1, sw2, w2, fw1, w3, fw2, w4);                        // 2

    // 3) h = relu(xs @ sw1^T + sb1) -> packed-tiled    <== ncu target
    gemm_mma<0><<<dim3(HS_ / 128, M1 / 128), 256, GEMM_SMEM>>>(                         // 3
        xsp, w1, sb1, nullptr, nullptr, h, M1, HS_, N_);

    // 4) y = h @ sw2^T + sb2 + xs -> fp32 (into xm)
    gemm_mma<1><<<dim3(N_ / 128, M1 / 128), 256, GEMM_SMEM>>>(
        h, w2, sb2, (const float*)xs, (float*)xm, nullptr, M1, N_, HS_);

    // 5) zt = gather(y, p) (into xsp as fp32)
    gather_k<<<M1, 512>>>((const float*)xm, (const int*)p, (float*)xsp);

    // 6) z[b,n,f] = zt[b,f,n] (into xs)
    transpose_k<<<dim3(N_ / 32, F_ / 32, B_), dim3(32, 8)>>>((const float*)xsp, (float*)xs, F_, N_);

    // 6b) pack z -> tiled (into xm)
    pack_k<<<(int)((size_t)M2 * F_ / 512), 256>>>((const float*)xs, xm, F_);

    // 7) h2 = relu(z @ fw1^T + fb1) -> packed-tiled (into h)
    gemm_mma<0><<<dim3(HF_ / 128, M2 / 128), 256, GEMM_SMEM>>>(
        xm, w3, fb1, nullptr, nullptr, h, M2, HF_, F_);

    // 8) out = h2 @ fw2^T + fb2 -> fp32
    gemm_mma<2><<<dim3(OUT_ / 128, M2 / 128), 256, GEMM_SMEM>>>(
        h, w4, fb2, nullptr, out, nullptr, M2, OUT_, HF_);
}

// round 16
// speedup vs baseline: 7.0329x; 1.1123x over previous
#include <cuda_runtime.h>
#include <cuda_fp16.h>
#include <cstdint>

#define B_   32
#define N_   2048
#define F_   1024
#define OUT_ 1024
#define HS_  8192
#define HF_  4096

// ---------------------------------------------------------------------------
// Scratch (__device__ globals; allocation-free rule).
// ---------------------------------------------------------------------------
__device__ __align__(1024) unsigned char g_xm [268435456];   // xm fp32 -> y fp32 -> z packed
__device__ __align__(1024) unsigned char g_xs [268435456];   // xs fp32 (skip)
__device__ __align__(1024) unsigned char g_xsp[268435456];   // xs packed-tiled -> zt fp32
__device__ __align__(1024) unsigned char g_p  [268435456];   // argsort indices (int)
__device__ __align__(1024) unsigned char g_h  [1073741824];  // h packed-tiled -> h2 packed-tiled
__device__ __align__(1024) unsigned char g_w1 [33554432];    // 8192x2048 fp16
__device__ __align__(1024) unsigned char g_w2 [33554432];    // 2048x8192 fp16
__device__ __align__(1024) unsigned char g_w3 [8388608];     // 4096x1024 fp16
__device__ __align__(1024) unsigned char g_w4 [8388608];     // 1024x4096 fp16

// ---------------------------------------------------------------------------
// PTX helpers (plain sm_90/sm_80 ISA — no 'a'-suffix features)
// ---------------------------------------------------------------------------
__device__ __forceinline__ uint32_t smem_u32(const void* p) {
    uint32_t a;
    asm("{ .reg .u64 t; cvta.to.shared.u64 t, %1; cvt.u32.u64 %0, t; }" : "=r"(a) : "l"(p));
    return a;
}
__device__ __forceinline__ void mbar_init(uint32_t m, uint32_t cnt) {
    asm volatile("mbarrier.init.shared.b64 [%0], %1;" :: "r"(m), "r"(cnt) : "memory");
}
__device__ __forceinline__ void mbar_wait(uint32_t m, uint32_t parity) {
    uint32_t done = 0;
    while (!done) {
        asm volatile(
            "{\n\t.reg .pred p;\n\t"
            "mbarrier.try_wait.parity.acquire.cta.shared::cta.b64 p, [%1], %2, 0x989680;\n\t"
            "selp.b32 %0, 1, 0, p;\n\t}"
            : "=r"(done) : "r"(m), "r"(parity) : "memory");
    }
}
__device__ __forceinline__ void mbar_arrive(uint32_t m) {
    asm volatile("mbarrier.arrive.shared.b64 _, [%0];" :: "r"(m) : "memory");
}
__device__ __forceinline__ void mbar_expect_tx(uint32_t m, uint32_t bytes) {
    asm volatile("mbarrier.arrive.expect_tx.shared.b64 _, [%0], %1;" :: "r"(m), "r"(bytes) : "memory");
}
__device__ __forceinline__ void bulk_cp(uint32_t dst, const void* src, uint32_t bytes, uint32_t mbar) {
    asm volatile("cp.async.bulk.shared::cta.global.mbarrier::complete_tx::bytes [%0], [%1], %2, [%3];"
                 :: "r"(dst), "l"(src), "r"(bytes), "r"(mbar) : "memory");
}
__device__ __forceinline__ void ldm_x4(uint32_t* r, uint32_t addr) {
    asm volatile("ldmatrix.sync.aligned.m8n8.x4.shared.b16 {%0,%1,%2,%3}, [%4];"
                 : "=r"(r[0]), "=r"(r[1]), "=r"(r[2]), "=r"(r[3]) : "r"(addr));
}
__device__ __forceinline__ void mma_f16(float* d, const uint32_t* a, uint32_t b0, uint32_t b1) {
    asm volatile("mma.sync.aligned.m16n8k16.row.col.f32.f16.f16.f32 "
                 "{%0,%1,%2,%3}, {%4,%5,%6,%7}, {%8,%9}, {%0,%1,%2,%3};"
                 : "+f"(d[0]), "+f"(d[1]), "+f"(d[2]), "+f"(d[3])
                 : "r"(a[0]), "r"(a[1]), "r"(a[2]), "r"(a[3]), "r"(b0), "r"(b1));
}

// ---------------------------------------------------------------------------
// Hi-only packed-tiled layout: rows in 128-groups, K in 64-groups.
// Tile (t, kc) = 16KB contiguous: 128 rows x 128B, row = 64 fp16 K-elems,
// byte offset pre-swizzled with o ^ ((row&7)<<4).
// ---------------------------------------------------------------------------
__device__ __forceinline__ void packed_store(unsigned char* base, int NC, int r, int k,
                                             float v0, float v1) {
    size_t tb = (((size_t)(r >> 7) * NC + (k >> 6)) * 128 + (r & 127)) * 128;
    int j2 = (k & 63) * 2;
    int swz = (r & 7) << 4;
    __half h0 = __float2half_rn(v0), h1 = __float2half_rn(v1);
    uint32_t hb = ((uint32_t)__half_as_ushort(h1) << 16) | __half_as_ushort(h0);
    *(uint32_t*)(base + tb + (j2 ^ swz)) = hb;
}

// ---------------------------------------------------------------------------
// transpose / sort / gather / packs
// ---------------------------------------------------------------------------
__global__ void transpose_k(const float* __restrict__ src, float* __restrict__ dst,
                            int R, int C) {
    __shared__ float tile[32][33];
    size_t bo = (size_t)blockIdx.z * R * C;
    int r0 = blockIdx.y * 32, c0 = blockIdx.x * 32;
    int tx = threadIdx.x, ty = threadIdx.y;
#pragma unroll
    for (int i = 0; i < 32; i += 8)
        tile[ty + i][tx] = src[bo + (size_t)(r0 + ty + i) * C + (c0 + tx)];
    __syncthreads();
#pragma unroll
    for (int i = 0; i < 32; i += 8)
        dst[bo + (size_t)(c0 + ty + i) * R + (r0 + tx)] = tile[tx][ty + i];
}

// register compare-exchange via shfl.bfly (partner in-warp, j <= 16)
__device__ __forceinline__ unsigned long long ce_reg(unsigned long long k, int e, int j, int k2) {
    unsigned long long o = __shfl_xor_sync(0xffffffffu, k, j);
    bool asc = ((e & k2) == 0);
    bool lower = ((e & j) == 0);
    bool takemin = (lower == asc);
    return takemin ? (k < o ? k : o) : (k > o ? k : o);
}

// Hybrid bitonic argsort of 2048-element rows.
// 1024 threads, 2 elems/thread (e = t and t+1024). Substeps with j<=16 run in
// registers via shfl (no smem, no bar); j>=32 via pair-mapped smem exchange.
__global__ __launch_bounds__(1024) void sort_k(const float* __restrict__ xm,
                                               float* __restrict__ xs,
                                               unsigned char* __restrict__ xsp,
                                               int* __restrict__ p) {
    __shared__ unsigned long long key[2048];
    __shared__ float val[2048];
    __shared__ int   rnk[2048];
    size_t base = (size_t)blockIdx.x * 2048;
    int t = threadIdx.x;

    unsigned long long k0, k1;
    {
        float v0 = xm[base + t], v1 = xm[base + t + 1024];
        val[t] = v0;
        val[t + 1024] = v1;
        unsigned u0 = __float_as_uint(v0);
        unsigned u1 = __float_as_uint(v1);
        u0 = (u0 & 0x80000000u) ? ~u0 : (u0 | 0x80000000u);
        u1 = (u1 & 0x80000000u) ? ~u1 : (u1 | 0x80000000u);
        k0 = ((unsigned long long)u0 << 32) | (unsigned)t;
        k1 = ((unsigned long long)u1 << 32) | (unsigned)(t + 1024);
    }

    // stages k2 = 2..32: fully in-register
#pragma unroll
    for (int k2 = 2; k2 <= 32; k2 <<= 1)
#pragma unroll
        for (int j = k2 >> 1; j >= 1; j >>= 1) {
            k0 = ce_reg(k0, t, j, k2);
            k1 = ce_reg(k1, t + 1024, j, k2);
        }
    key[t] = k0;
    key[t + 1024] = k1;
    __syncthreads();

    // stages k2 = 64..2048: j>=32 via smem, then j=16..1 tail in registers
    for (int k2 = 64; k2 <= 2048; k2 <<= 1) {
        for (int j = k2 >> 1; j >= 32; j >>= 1) {
            int i = ((t & ~(j - 1)) << 1) | (t & (j - 1));
            unsigned long long a = key[i], b = key[i + j];
            bool asc = ((i & k2) == 0);
            if ((a > b) == asc) { key[i] = b; key[i + j] = a; }
            __syncthreads();
        }
        k0 = key[t];
        k1 = key[t + 1024];
#pragma unroll
        for (int j = 16; j >= 1; j >>= 1) {
            k0 = ce_reg(k0, t, j, k2);
            k1 = ce_reg(k1, t + 1024, j, k2);
        }
        key[t] = k0;
        key[t + 1024] = k1;
        __syncthreads();
    }

    // outputs: p, inverse ranks, xs (fp32 skip) + packed xs
    for (int i = t; i < 2048; i += 1024) {
        int pi = (int)(unsigned)(key[i] & 0xffffffffu);
        p[base + i] = pi;
        rnk[pi] = i;
    }
    __syncthreads();
    {
        int i = 2 * t;
        float v0 = val[rnk[i]], v1 = val[rnk[i + 1]];
        xs[base + i] = v0;
        xs[base + i + 1] = v1;
        packed_store(xsp, 32, blockIdx.x, i, v0, v1);   // NC = 2048/64
    }
}

__global__ __launch_bounds__(512) void gather_k(const float* __restrict__ y,
                                                const int* __restrict__ p,
                                                float* __restrict__ zt) {
    size_t base = (size_t)blockIdx.x * 2048;
    for (int n = threadIdx.x; n < 2048; n += 512)
        zt[base + n] = y[base + p[base + n]];
}

// fused transpose + pack: zt [B,F,N] fp32 -> packed z rows r=b*2048+n, k=f
__global__ void tp_k(const float* __restrict__ src, unsigned char* __restrict__ out) {
    __shared__ float tile[32][33];
    int b = blockIdx.z;
    int f0 = blockIdx.x * 32, n0 = blockIdx.y * 32;
    int tx = threadIdx.x, ty = threadIdx.y;   // 32 x 8
    size_t bo = (size_t)b * F_ * N_;
#pragma unroll
    for (int i = 0; i < 32; i += 8)
        tile[ty + i][tx] = src[bo + (size_t)(f0 + ty + i) * N_ + n0 + tx];
    __syncthreads();
    int tid = ty * 32 + tx;
    int nn = tid >> 3;      // 0..31
    int pp0 = tid & 7;      // 0..7
    int r = b * 2048 + n0 + nn;
#pragma unroll
    for (int q = 0; q < 2; q++) {
        int pp = pp0 + q * 8;   // 0..15
        packed_store(out, F_ / 64, r, f0 + 2 * pp, tile[2 * pp][nn], tile[2 * pp + 1][nn]);
    }
}

__device__ __forceinline__ void pack_body(const float* __restrict__ in,
                                          unsigned char* __restrict__ out,
                                          int K, int bid, int tid) {
    size_t gid = (size_t)bid * 256 + tid;
    size_t r = gid / (unsigned)(K / 2);
    int k = (int)(gid - r * (unsigned)(K / 2)) * 2;
    const float* row = in + r * (size_t)K;
    packed_store(out, K / 64, (int)r, k, row[k], row[k + 1]);
}

// weight packs split in two launches (puts sort_k at my launch index 3 for ncu)
__global__ __launch_bounds__(256) void packWa_k(const float* __restrict__ sw1, unsigned char* __restrict__ o1,
                                                const float* __restrict__ sw2, unsigned char* __restrict__ o2) {
    int b = blockIdx.x, t = threadIdx.x;
    if (b < 32768) pack_body(sw1, o1, N_,  b,         t);
    else           pack_body(sw2, o2, HS_, b - 32768, t);
}
__global__ __launch_bounds__(256) void packWb_k(const float* __restrict__ fw1, unsigned char* __restrict__ o3,
                                                const float* __restrict__ fw2, unsigned char* __restrict__ o4) {
    int b = blockIdx.x, t = threadIdx.x;
    if (b < 8192) pack_body(fw1, o3, F_,  b,        t);
    else          pack_body(fw2, o4, HF_, b - 8192, t);
}

// ---------------------------------------------------------------------------
// fp16 single-pass mma.sync GEMM on hi-only layout (chunk = 64 K-elems).
// CTA tile 128x128, 256 thr, warp tile 32x64, 2 CTAs/SM, S_=3 stages.
// MODE 0: bias+relu -> packed-tiled. MODE 1: bias+skip fp32. MODE 2: bias fp32.
// ---------------------------------------------------------------------------
#define S_ 3
#define STAGE_B 32768
#define GEMM_SMEM (1024 + S_ * STAGE_B)

template <int MODE>
__global__ __launch_bounds__(256, 2) void gemm_mma(
    const unsigned char* __restrict__ Ap, const unsigned char* __restrict__ Bp,
    const float* __restrict__ bias, const float* __restrict__ Skip,
    float* __restrict__ Cf, unsigned char* __restrict__ Cp,
    int M, int Ntot, int K) {
    extern __shared__ __align__(1024) unsigned char smem_raw[];
    const uint32_t sb = smem_u32(smem_raw);
    const int tid = threadIdx.x;
    const int lane = tid & 31, wid = tid >> 5;
    const int wm = wid & 3, wn = wid >> 2;         // 4 x 2 warp grid (M x N)
    const int NC = K / 64;
    const int m0 = blockIdx.y * 128, n0 = blockIdx.x * 128;

    const uint32_t FULL0 = sb;            // full[s] at sb+16s, free[s] at sb+16s+8
    const uint32_t DATA  = sb + 1024;

    if (tid == 0) {
        for (int s = 0; s < S_; s++) {
            mbar_init(FULL0 + 16 * s, 1);
            mbar_init(FULL0 + 16 * s + 8, 256);
        }
        asm volatile("fence.proxy.async.shared::cta;" ::: "memory");
    }
    __syncthreads();

    const unsigned char* Atile = Ap + (size_t)blockIdx.y * NC * 16384;
    const unsigned char* Btile = Bp + (size_t)blockIdx.x * NC * 16384;

    if (tid == 0) {
#pragma unroll
        for (int s = 0; s < S_ - 1; s++) {
            if (s < NC) {
                uint32_t st = DATA + (uint32_t)s * STAGE_B;
                mbar_expect_tx(FULL0 + 16 * s, STAGE_B);
                bulk_cp(st,          Atile + (size_t)s * 16384, 16384u, FULL0 + 16 * s);
                bulk_cp(st + 16384u, Btile + (size_t)s * 16384, 16384u, FULL0 + 16 * s);
            }
        }
    }

    float acc[2][8][4];
#pragma unroll
    for (int a = 0; a < 2; a++)
#pragma unroll
        for (int b = 0; b < 8; b++)
#pragma unroll
            for (int c = 0; c < 4; c++) acc[a][b][c] = 0.f;

    const int lr = lane & 15;
    const int lh = (lane >> 4) << 4;

    for (int kc = 0; kc < NC; kc++) {
        const int s = kc % S_;
        if (tid == 0) {
            int kp = kc + S_ - 1;
            if (kp < NC) {
                int sp = kp % S_;
                if (kp >= S_) mbar_wait(FULL0 + 16 * sp + 8, ((kp / S_) - 1) & 1);
                uint32_t st = DATA + (uint32_t)sp * STAGE_B;
                mbar_expect_tx(FULL0 + 16 * sp, STAGE_B);
                bulk_cp(st,          Atile + (size_t)kp * 16384, 16384u, FULL0 + 16 * sp);
                bulk_cp(st + 16384u, Btile + (size_t)kp * 16384, 16384u, FULL0 + 16 * sp);
            }
        }
        mbar_wait(FULL0 + 16 * s, (kc / S_) & 1);

        const uint32_t Ab = DATA + (uint32_t)s * STAGE_B;
        const uint32_t Bb = Ab + 16384u;

        // 64 K-elems per chunk = two 32-elem halves (keeps register footprint)
#pragma unroll
        for (int half = 0; half < 2; half++) {
            const int off = half * 64;   // byte offset within 128B row
            uint32_t a[2][2][4];   // [ks][mt]
            uint32_t bh[2][4][4];  // [ks][nq]
#pragma unroll
            for (int ks = 0; ks < 2; ks++)
#pragma unroll
                for (int mt = 0; mt < 2; mt++) {
                    int row = wm * 32 + mt * 16 + lr;
                    ldm_x4(a[ks][mt], Ab + row * 128 + ((off + ks * 32 + lh) ^ ((row & 7) << 4)));
                }
#pragma unroll
            for (int ks = 0; ks < 2; ks++)
#pragma unroll
                for (int nq = 0; nq < 4; nq++) {
                    int row = wn * 64 + nq * 16 + lr;
                    ldm_x4(bh[ks][nq], Bb + row * 128 + ((off + ks * 32 + lh) ^ ((row & 7) << 4)));
                }
#pragma unroll
            for (int ks = 0; ks < 2; ks++)
#pragma unroll
                for (int mt = 0; mt < 2; mt++)
#pragma unroll
                    for (int nq = 0; nq < 4; nq++) {
                        mma_f16(acc[mt][2 * nq],     a[ks][mt], bh[ks][nq][0], bh[ks][nq][2]);
                        mma_f16(acc[mt][2 * nq + 1], a[ks][mt], bh[ks][nq][1], bh[ks][nq][3]);
                    }
        }
        mbar_arrive(FULL0 + 16 * s + 8);
    }

    // ---- epilogue ----
    const int NCo = Ntot / 64;
#pragma unroll
    for (int mt = 0; mt < 2; mt++) {
        int r0 = m0 + wm * 32 + mt * 16 + (lane >> 2);
#pragma unroll
        for (int nf = 0; nf < 8; nf++) {
            int c = n0 + wn * 64 + nf * 8 + (lane & 3) * 2;
            float b0 = bias[c], b1v = bias[c + 1];
            float v00 = acc[mt][nf][0] + b0, v01 = acc[mt][nf][1] + b1v;
            float v10 = acc[mt][nf][2] + b0, v11 = acc[mt][nf][3] + b1v;
            int r1 = r0 + 8;
            if (MODE == 0) {
                packed_store(Cp, NCo, r0, c, fmaxf(v00, 0.f), fmaxf(v01, 0.f));
                packed_store(Cp, NCo, r1, c, fmaxf(v10, 0.f), fmaxf(v11, 0.f));
            } else if (MODE == 1) {
                const float2 s0 = *(const float2*)(Skip + (size_t)r0 * Ntot + c);
                const float2 s1 = *(const float2*)(Skip + (size_t)r1 * Ntot + c);
                *(float2*)(Cf + (size_t)r0 * Ntot + c) = make_float2(v00 + s0.x, v01 + s0.y);
                *(float2*)(Cf + (size_t)r1 * Ntot + c) = make_float2(v10 + s1.x, v11 + s1.y);
            } else {
                *(float2*)(Cf + (size_t)r0 * Ntot + c) = make_float2(v00, v01);
                *(float2*)(Cf + (size_t)r1 * Ntot + c) = make_float2(v10, v11);
            }
        }
    }
}

// ---------------------------------------------------------------------------
extern "C" void kernel_launch(void* const* d_in, const int* in_sizes, int n_in,
                              void* d_out, int out_size) {
    const float* x   = (const float*)d_in[0];
    const float* sw1 = (const float*)d_in[1];
    const float* sb1 = (const float*)d_in[2];
    const float* sw2 = (const float*)d_in[3];
    const float* sb2 = (const float*)d_in[4];
    const float* fw1 = (const float*)d_in[5];
    const float* fb1 = (const float*)d_in[6];
    const float* fw2 = (const float*)d_in[7];
    const float* fb2 = (const float*)d_in[8];
    float* out = (float*)d_out;

    unsigned char *xm, *xs, *xsp, *p, *h, *w1, *w2, *w3, *w4;
    cudaGetSymbolAddress((void**)&xm,  g_xm);
    cudaGetSymbolAddress((void**)&xs,  g_xs);
    cudaGetSymbolAddress((void**)&xsp, g_xsp);
    cudaGetSymbolAddress((void**)&p,   g_p);
    cudaGetSymbolAddress((void**)&h,   g_h);
    cudaGetSymbolAddress((void**)&w1,  g_w1);
    cudaGetSymbolAddress((void**)&w2,  g_w2);
    cudaGetSymbolAddress((void**)&w3,  g_w3);
    cudaGetSymbolAddress((void**)&w4,  g_w4);

    cudaFuncSetAttribute((const void*)gemm_mma<0>, cudaFuncAttributeMaxDynamicSharedMemorySize, GEMM_SMEM);
    cudaFuncSetAttribute((const void*)gemm_mma<1>, cudaFuncAttributeMaxDynamicSharedMemorySize, GEMM_SMEM);
    cudaFuncSetAttribute((const void*)gemm_mma<2>, cudaFuncAttributeMaxDynamicSharedMemorySize, GEMM_SMEM);

    const int M1 = B_ * F_;   // 32768
    const int M2 = B_ * N_;   // 65536

    // my launch index (ncu -s 5 with 2 hidden launches => profiles idx 3 = sort_k)
    packWa_k<<<65536, 256>>>(sw1, w1, sw2, w2);                                         // 0
    packWb_k<<<16384, 256>>>(fw1, w3, fw2, w4);                                         // 1
    transpose_k<<<dim3(F_ / 32, N_ / 32, B_), dim3(32, 8)>>>(x, (float*)xm, N_, F_);    // 2
    sort_k<<<M1, 1024>>>((const float*)xm, (float*)xs, xsp, (int*)p);                   // 3  <== ncu

    // h = relu(xs @ sw1^T + sb1) -> packed-tiled
    gemm_mma<0><<<dim3(HS_ / 128, M1 / 128), 256, GEMM_SMEM>>>(
        xsp, w1, sb1, nullptr, nullptr, h, M1, HS_, N_);

    // y = h @ sw2^T + sb2 + xs -> fp32 (into xm)
    gemm_mma<1><<<dim3(N_ / 128, M1 / 128), 256, GEMM_SMEM>>>(
        h, w2, sb2, (const float*)xs, (float*)xm, nullptr, M1, N_, HS_);

    // zt = gather(y, p) (into xsp as fp32)
    gather_k<<<M1, 512>>>((const float*)xm, (const int*)p, (float*)xsp);

    // fused transpose+pack: zt -> packed z (into xm)
    tp_k<<<dim3(F_ / 32, N_ / 32, B_), dim3(32, 8)>>>((const float*)xsp, xm);

    // h2 = relu(z @ fw1^T + fb1) -> packed-tiled (into h)
    gemm_mma<0><<<dim3(HF_ / 128, M2 / 128), 256, GEMM_SMEM>>>(
        xm, w3, fb1, nullptr, nullptr, h, M2, HF_, F_);

    // out = h2 @ fw2^T + fb2 -> fp32
    gemm_mma<2><<<dim3(OUT_ / 128, M2 / 128), 256, GEMM_SMEM>>>(
        h, w4, fb2, nullptr, out, nullptr, M2, OUT_, HF_);
}